// round 14
// baseline (speedup 1.0000x reference)
#include <cuda_runtime.h>
#include <cuda_bf16.h>
#include <cstdint>

#define N_NODES 50000
#define MAX_E   800000
#define D_IN    128
#define D_HID   256
#define D_OUT   128
#define NBLK_SCAN ((N_NODES + 1023) / 1024)   // 49
#define XQ4 ((N_NODES * D_IN) / 4)            // 1.6M float4 groups in x

// ---------------- scratch (static device globals; no allocation) ----------------
__device__ float g_neigh1[(size_t)N_NODES * D_IN];
__device__ float g_h1[(size_t)N_NODES * D_HID];
__device__ float g_s2[(size_t)N_NODES * D_OUT];
__device__ __nv_bfloat16 g_xb[(size_t)N_NODES * D_IN];     // x in bf16 (gather-only)
__device__ __nv_bfloat16 g_t2b[(size_t)N_NODES * D_OUT];   // t2 in bf16 (gather-only)
__device__ float g_sA[N_NODES];
__device__ float g_sB[N_NODES];
__device__ int   g_cnt[N_NODES];
__device__ int   g_rowptr[N_NODES + 1];
__device__ int   g_cursor[N_NODES];
__device__ int   g_csr_src[MAX_E];
__device__ int   g_blksum[64];

// pre-split bf16 weights, same (K,N) layout as the fp32 originals
__device__ __nv_bfloat16 g_w1s_h[D_IN * D_HID], g_w1s_l[D_IN * D_HID];
__device__ __nv_bfloat16 g_w1n_h[D_IN * D_HID], g_w1n_l[D_IN * D_HID];
__device__ __nv_bfloat16 g_w2s_h[D_HID * D_OUT], g_w2s_l[D_HID * D_OUT];
__device__ __nv_bfloat16 g_w2n_h[D_HID * D_OUT], g_w2n_l[D_HID * D_OUT];

// ---------------- helpers ----------------
__device__ __forceinline__ uint32_t smem_u32(const void* p) {
    uint32_t a;
    asm("{ .reg .u64 t; cvta.to.shared.u64 t, %1; cvt.u32.u64 %0, t; }" : "=r"(a) : "l"(p));
    return a;
}
__device__ __forceinline__ uint32_t bpack(__nv_bfloat16 a, __nv_bfloat16 b) {
    return (uint32_t)__bfloat16_as_ushort(a) | ((uint32_t)__bfloat16_as_ushort(b) << 16);
}
__device__ __forceinline__ void split4(float4 v, uint32_t* h, uint32_t* l) {
    __nv_bfloat16 hx = __float2bfloat16_rn(v.x);
    __nv_bfloat16 hy = __float2bfloat16_rn(v.y);
    __nv_bfloat16 hz = __float2bfloat16_rn(v.z);
    __nv_bfloat16 hw = __float2bfloat16_rn(v.w);
    h[0] = bpack(hx, hy);
    h[1] = bpack(hz, hw);
    __nv_bfloat16 lx = __float2bfloat16_rn(v.x - __bfloat162float(hx));
    __nv_bfloat16 ly = __float2bfloat16_rn(v.y - __bfloat162float(hy));
    __nv_bfloat16 lz = __float2bfloat16_rn(v.z - __bfloat162float(hz));
    __nv_bfloat16 lw = __float2bfloat16_rn(v.w - __bfloat162float(hw));
    l[0] = bpack(lx, ly);
    l[1] = bpack(lz, lw);
}
__device__ __forceinline__ void acc_bf16x8(float* acc, uint4 v) {
    float2 f;
    f = __bfloat1622float2(*(__nv_bfloat162*)&v.x); acc[0] += f.x; acc[1] += f.y;
    f = __bfloat1622float2(*(__nv_bfloat162*)&v.y); acc[2] += f.x; acc[3] += f.y;
    f = __bfloat1622float2(*(__nv_bfloat162*)&v.z); acc[4] += f.x; acc[5] += f.y;
    f = __bfloat1622float2(*(__nv_bfloat162*)&v.w); acc[6] += f.x; acc[7] += f.y;
}

#define LDSM_X4(r0, r1, r2, r3, addr) \
    asm volatile("ldmatrix.sync.aligned.m8n8.x4.shared.b16 {%0,%1,%2,%3}, [%4];" \
                 : "=r"(r0), "=r"(r1), "=r"(r2), "=r"(r3) : "r"(addr))
#define LDSM_X4T(r0, r1, r2, r3, addr) \
    asm volatile("ldmatrix.sync.aligned.m8n8.x4.trans.shared.b16 {%0,%1,%2,%3}, [%4];" \
                 : "=r"(r0), "=r"(r1), "=r"(r2), "=r"(r3) : "r"(addr))
#define MMA_BF16(c, a, b) \
    asm volatile("mma.sync.aligned.m16n8k16.row.col.f32.bf16.bf16.f32 " \
                 "{%0,%1,%2,%3}, {%4,%5,%6,%7}, {%8,%9}, {%0,%1,%2,%3};" \
                 : "+f"((c)[0]), "+f"((c)[1]), "+f"((c)[2]), "+f"((c)[3]) \
                 : "r"((a)[0]), "r"((a)[1]), "r"((a)[2]), "r"((a)[3]), \
                   "r"((b)[0]), "r"((b)[1]))
#define CP_ASYNC16(saddr, gptr) \
    asm volatile("cp.async.cg.shared.global [%0], [%1], 16;" :: "r"(saddr), "l"(gptr))
#define CP_COMMIT() asm volatile("cp.async.commit_group;")
#define CP_WAIT(n)  asm volatile("cp.async.wait_group %0;" :: "n"(n))

// ---------------- CSR build ----------------
__global__ void k_hist(const int* __restrict__ dst, int E) {
    int e = blockIdx.x * blockDim.x + threadIdx.x;
    if (e < E) atomicAdd(&g_cnt[dst[e]], 1);
}

__global__ void k_scan1() {
    __shared__ int sh[1024];
    int t = threadIdx.x;
    int idx = blockIdx.x * 1024 + t;
    sh[t] = (idx < N_NODES) ? g_cnt[idx] : 0;
    __syncthreads();
#pragma unroll
    for (int off = 512; off > 0; off >>= 1) {
        if (t < off) sh[t] += sh[t + off];
        __syncthreads();
    }
    if (t == 0) g_blksum[blockIdx.x] = sh[0];
}

// merged phase 2+3 with shfl scans
__global__ void k_scan3() {
    __shared__ int bs[64];
    __shared__ int wscan[32];
    int t = threadIdx.x, lane = t & 31, w = t >> 5;

    if (w == 0) {
        int a0 = (lane < NBLK_SCAN) ? g_blksum[lane] : 0;
        int a1 = (lane + 32 < NBLK_SCAN) ? g_blksum[lane + 32] : 0;
#pragma unroll
        for (int off = 1; off < 32; off <<= 1) {
            int u = __shfl_up_sync(0xFFFFFFFFu, a0, off);
            if (lane >= off) a0 += u;
        }
        int tot0 = __shfl_sync(0xFFFFFFFFu, a0, 31);
#pragma unroll
        for (int off = 1; off < 32; off <<= 1) {
            int u = __shfl_up_sync(0xFFFFFFFFu, a1, off);
            if (lane >= off) a1 += u;
        }
        a1 += tot0;
        bs[lane] = a0;
        bs[lane + 32] = a1;
    }
    __syncthreads();
    int blk_off = (blockIdx.x == 0) ? 0 : bs[blockIdx.x - 1];
    if (blockIdx.x == 0 && t == 0) g_rowptr[N_NODES] = bs[NBLK_SCAN - 1];

    int idx = blockIdx.x * 1024 + t;
    int v = (idx < N_NODES) ? g_cnt[idx] : 0;
    int iv = v;
#pragma unroll
    for (int off = 1; off < 32; off <<= 1) {
        int u = __shfl_up_sync(0xFFFFFFFFu, iv, off);
        if (lane >= off) iv += u;
    }
    if (lane == 31) wscan[w] = iv;
    __syncthreads();
    if (w == 0) {
        int s = wscan[lane];
#pragma unroll
        for (int off = 1; off < 32; off <<= 1) {
            int u = __shfl_up_sync(0xFFFFFFFFu, s, off);
            if (lane >= off) s += u;
        }
        wscan[lane] = s;
    }
    __syncthreads();
    int warp_off = (w == 0) ? 0 : wscan[w - 1];
    if (idx < N_NODES) {
        int ex = iv - v + warp_off + blk_off;
        g_rowptr[idx] = ex;
        g_cursor[idx] = ex;
    }
}

__global__ void k_fill(const int* __restrict__ src, const int* __restrict__ dst, int E) {
    int e = blockIdx.x * blockDim.x + threadIdx.x;
    if (e < E) {
        int d = dst[e];
        int pos = atomicAdd(&g_cursor[d], 1);
        g_csr_src[pos] = src[e];
    }
}

// ---------------- prep: cnt zero + weight split + x->bf16, one launch ----------------
__global__ void k_prep_all(
    const float* __restrict__ W1s, const float* __restrict__ W1n,
    const float* __restrict__ W2s, const float* __restrict__ W2n,
    const float* __restrict__ x)
{
    int i = blockIdx.x * blockDim.x + threadIdx.x;
    if (i < N_NODES) g_cnt[i] = 0;
    if (i < 4 * 32768) {
        int a = i >> 15, r = i & 32767;
        const float* W = (a == 0) ? W1s : (a == 1) ? W1n : (a == 2) ? W2s : W2n;
        __nv_bfloat16* hi = (a == 0) ? g_w1s_h : (a == 1) ? g_w1n_h : (a == 2) ? g_w2s_h : g_w2n_h;
        __nv_bfloat16* lo = (a == 0) ? g_w1s_l : (a == 1) ? g_w1n_l : (a == 2) ? g_w2s_l : g_w2n_l;
        float w = W[r];
        __nv_bfloat16 h = __float2bfloat16_rn(w);
        hi[r] = h;
        lo[r] = __float2bfloat16_rn(w - __bfloat162float(h));
    }
    if (i < XQ4) {
        float4 v = ((const float4*)x)[i];
        uint2 o;
        o.x = bpack(__float2bfloat16_rn(v.x), __float2bfloat16_rn(v.y));
        o.y = bpack(__float2bfloat16_rn(v.z), __float2bfloat16_rn(v.w));
        ((uint2*)g_xb)[i] = o;
    }
}

// ---------------- layer-1 aggregation: half-warp per node, bf16 x gather ----------------
__global__ void k_agg128(float* __restrict__ out) {
    int halves_per_blk = blockDim.x >> 4;
    int n = blockIdx.x * halves_per_blk + (threadIdx.x >> 4);
    if (n >= N_NODES) return;
    int lane = threadIdx.x & 15;
    int beg = g_rowptr[n], end = g_rowptr[n + 1];

    float a0[8] = {0.f, 0.f, 0.f, 0.f, 0.f, 0.f, 0.f, 0.f};
    float a1[8] = {0.f, 0.f, 0.f, 0.f, 0.f, 0.f, 0.f, 0.f};
    int j = beg;
    for (; j + 1 < end; j += 2) {
        int s0 = g_csr_src[j];
        int s1 = g_csr_src[j + 1];
        uint4 v0 = __ldg(&((const uint4*)(g_xb + (size_t)s0 * 128))[lane]);
        uint4 v1 = __ldg(&((const uint4*)(g_xb + (size_t)s1 * 128))[lane]);
        acc_bf16x8(a0, v0);
        acc_bf16x8(a1, v1);
    }
    if (j < end) {
        int s0 = g_csr_src[j];
        uint4 v0 = __ldg(&((const uint4*)(g_xb + (size_t)s0 * 128))[lane]);
        acc_bf16x8(a0, v0);
    }
#pragma unroll
    for (int q = 0; q < 8; q++) a0[q] += a1[q];
    int deg = end - beg;
    float inv = (deg > 0) ? 1.f / (float)deg : 0.f;
    float4* orow = (float4*)(out + (size_t)n * 128);
    float4 o0 = {a0[0] * inv, a0[1] * inv, a0[2] * inv, a0[3] * inv};
    float4 o1 = {a0[4] * inv, a0[5] * inv, a0[6] * inv, a0[7] * inv};
    orow[lane * 2] = o0;
    orow[lane * 2 + 1] = o1;
}

// ================= bf16x3 mma.sync GEMMs: swizzled-B double-buffer =================
#define A_TILE_B 10240
#define B_TILE_B 4096

// -------- layer 1: C = relu(A1@B1 + A2@B2 + bias) --------
__global__ void __launch_bounds__(256) k_mm_dual(
    const float* __restrict__ A1, const float* __restrict__ A2,
    const __nv_bfloat16* __restrict__ B1h, const __nv_bfloat16* __restrict__ B1l,
    const __nv_bfloat16* __restrict__ B2h, const __nv_bfloat16* __restrict__ B2l,
    const float* __restrict__ bias, float* __restrict__ C,
    int M, int N, int K)
{
    extern __shared__ char smem[];
    const int OA1H = 0, OA1L = A_TILE_B, OA2H = 2 * A_TILE_B, OA2L = 3 * A_TILE_B;
    const int OB_BASE = 4 * A_TILE_B;
    uint32_t sb = smem_u32(smem);

    int tid = threadIdx.x, lane = tid & 31, wid = tid >> 5;
    int wm = wid & 3, wn = wid >> 2;
    int bm = blockIdx.y * 128, bn = blockIdx.x * 64;
    const int nch = K >> 5;

    int brow = tid >> 3, bseg = tid & 7;
    uint32_t bso = (uint32_t)(brow * 128 + ((bseg ^ (brow & 7)) << 4));
    const __nv_bfloat16* gB[4] = {B1h, B1l, B2h, B2l};

    float acc[2][4][4];
#pragma unroll
    for (int i = 0; i < 2; i++)
#pragma unroll
        for (int j = 0; j < 4; j++)
#pragma unroll
            for (int q = 0; q < 4; q++) acc[i][j][q] = 0.f;

    {
        size_t ge = (size_t)brow * N + bn + bseg * 8;
#pragma unroll
        for (int t = 0; t < 4; t++)
            CP_ASYNC16(sb + OB_BASE + t * B_TILE_B + bso, gB[t] + ge);
        CP_COMMIT();
    }

    for (int chunk = 0; chunk < nch; chunk++) {
        int k0 = chunk << 5;
        int obuf = OB_BASE + (chunk & 1) * 4 * B_TILE_B;

#pragma unroll
        for (int q = 0; q < 4; q++) {
            int slot = tid + q * 256;
            int row = slot >> 3, k4 = (slot & 7) * 4;
            int gr = bm + row;
            float4 v1 = {0.f, 0.f, 0.f, 0.f}, v2 = {0.f, 0.f, 0.f, 0.f};
            if (gr < M) {
                v1 = *(const float4*)(A1 + (size_t)gr * K + k0 + k4);
                v2 = *(const float4*)(A2 + (size_t)gr * K + k0 + k4);
            }
            uint32_t h[2], l[2];
            int si = row * 20 + (k4 >> 1);
            split4(v1, h, l);
            ((uint32_t*)(smem + OA1H))[si] = h[0];
            ((uint32_t*)(smem + OA1H))[si + 1] = h[1];
            ((uint32_t*)(smem + OA1L))[si] = l[0];
            ((uint32_t*)(smem + OA1L))[si + 1] = l[1];
            split4(v2, h, l);
            ((uint32_t*)(smem + OA2H))[si] = h[0];
            ((uint32_t*)(smem + OA2H))[si + 1] = h[1];
            ((uint32_t*)(smem + OA2L))[si] = l[0];
            ((uint32_t*)(smem + OA2L))[si + 1] = l[1];
        }

        if (chunk + 1 < nch) {
            int nbuf = OB_BASE + ((chunk + 1) & 1) * 4 * B_TILE_B;
            size_t ge = (size_t)(((chunk + 1) << 5) + brow) * N + bn + bseg * 8;
#pragma unroll
            for (int t = 0; t < 4; t++)
                CP_ASYNC16(sb + nbuf + t * B_TILE_B + bso, gB[t] + ge);
            CP_COMMIT();
            CP_WAIT(1);
        } else {
            CP_WAIT(0);
        }
        __syncthreads();

#pragma unroll
        for (int kk = 0; kk < 2; kk++) {
            uint32_t fa1h[2][4], fa1l[2][4], fa2h[2][4], fa2l[2][4];
#pragma unroll
            for (int mi = 0; mi < 2; mi++) {
                uint32_t aoff = (uint32_t)((wm * 32 + mi * 16 + (lane & 15)) * 80 +
                                           (lane >> 4) * 16 + kk * 32);
                LDSM_X4(fa1h[mi][0], fa1h[mi][1], fa1h[mi][2], fa1h[mi][3], sb + OA1H + aoff);
                LDSM_X4(fa1l[mi][0], fa1l[mi][1], fa1l[mi][2], fa1l[mi][3], sb + OA1L + aoff);
                LDSM_X4(fa2h[mi][0], fa2h[mi][1], fa2h[mi][2], fa2h[mi][3], sb + OA2H + aoff);
                LDSM_X4(fa2l[mi][0], fa2l[mi][1], fa2l[mi][2], fa2l[mi][3], sb + OA2L + aoff);
            }
            uint32_t fb1h[4][2], fb1l[4][2], fb2h[4][2], fb2l[4][2];
#pragma unroll
            for (int np = 0; np < 2; np++) {
                int r = kk * 16 + (lane & 7) + ((lane >> 3) & 1) * 8;
                int cu = wn * 4 + np * 2 + (lane >> 4);
                uint32_t boff = (uint32_t)(r * 128 + ((cu ^ (r & 7)) << 4));
                LDSM_X4T(fb1h[2 * np][0], fb1h[2 * np][1], fb1h[2 * np + 1][0], fb1h[2 * np + 1][1], sb + obuf + 0 * B_TILE_B + boff);
                LDSM_X4T(fb1l[2 * np][0], fb1l[2 * np][1], fb1l[2 * np + 1][0], fb1l[2 * np + 1][1], sb + obuf + 1 * B_TILE_B + boff);
                LDSM_X4T(fb2h[2 * np][0], fb2h[2 * np][1], fb2h[2 * np + 1][0], fb2h[2 * np + 1][1], sb + obuf + 2 * B_TILE_B + boff);
                LDSM_X4T(fb2l[2 * np][0], fb2l[2 * np][1], fb2l[2 * np + 1][0], fb2l[2 * np + 1][1], sb + obuf + 3 * B_TILE_B + boff);
            }
#pragma unroll
            for (int mi = 0; mi < 2; mi++)
#pragma unroll
                for (int nj = 0; nj < 4; nj++) {
                    MMA_BF16(acc[mi][nj], fa1h[mi], fb1h[nj]);
                    MMA_BF16(acc[mi][nj], fa1h[mi], fb1l[nj]);
                    MMA_BF16(acc[mi][nj], fa1l[mi], fb1h[nj]);
                    MMA_BF16(acc[mi][nj], fa2h[mi], fb2h[nj]);
                    MMA_BF16(acc[mi][nj], fa2h[mi], fb2l[nj]);
                    MMA_BF16(acc[mi][nj], fa2l[mi], fb2h[nj]);
                }
        }
        __syncthreads();
    }

    int g = lane >> 2, c2 = (lane & 3) * 2;
#pragma unroll
    for (int mi = 0; mi < 2; mi++)
#pragma unroll
        for (int nj = 0; nj < 4; nj++) {
            int col = bn + wn * 32 + nj * 8 + c2;
            float2 bv = *(const float2*)(bias + col);
            int r0 = bm + wm * 32 + mi * 16 + g;
            if (r0 < M) {
                float2 o;
                o.x = fmaxf(acc[mi][nj][0] + bv.x, 0.f);
                o.y = fmaxf(acc[mi][nj][1] + bv.y, 0.f);
                *(float2*)(C + (size_t)r0 * N + col) = o;
            }
            int r1 = r0 + 8;
            if (r1 < M) {
                float2 o;
                o.x = fmaxf(acc[mi][nj][2] + bv.x, 0.f);
                o.y = fmaxf(acc[mi][nj][3] + bv.y, 0.f);
                *(float2*)(C + (size_t)r1 * N + col) = o;
            }
        }
}

// -------- layer 2: S = A@Bs + bias (fp32), T = A@Bt (bf16) --------
__global__ void __launch_bounds__(256) k_mm_pair(
    const float* __restrict__ A,
    const __nv_bfloat16* __restrict__ Bsh, const __nv_bfloat16* __restrict__ Bsl,
    const __nv_bfloat16* __restrict__ Bth, const __nv_bfloat16* __restrict__ Btl,
    const float* __restrict__ bias, float* __restrict__ S, __nv_bfloat16* __restrict__ T,
    int M, int N, int K)
{
    extern __shared__ char smem[];
    const int OAH = 0, OAL = A_TILE_B;
    const int OB_BASE = 2 * A_TILE_B;
    uint32_t sb = smem_u32(smem);

    int tid = threadIdx.x, lane = tid & 31, wid = tid >> 5;
    int wm = wid & 3, wn = wid >> 2;
    int bm = blockIdx.y * 128, bn = blockIdx.x * 64;
    const int nch = K >> 5;

    int brow = tid >> 3, bseg = tid & 7;
    uint32_t bso = (uint32_t)(brow * 128 + ((bseg ^ (brow & 7)) << 4));
    const __nv_bfloat16* gB[4] = {Bsh, Bsl, Bth, Btl};

    float accS[2][4][4], accT[2][4][4];
#pragma unroll
    for (int i = 0; i < 2; i++)
#pragma unroll
        for (int j = 0; j < 4; j++)
#pragma unroll
            for (int q = 0; q < 4; q++) { accS[i][j][q] = 0.f; accT[i][j][q] = 0.f; }

    {
        size_t ge = (size_t)brow * N + bn + bseg * 8;
#pragma unroll
        for (int t = 0; t < 4; t++)
            CP_ASYNC16(sb + OB_BASE + t * B_TILE_B + bso, gB[t] + ge);
        CP_COMMIT();
    }

    for (int chunk = 0; chunk < nch; chunk++) {
        int k0 = chunk << 5;
        int obuf = OB_BASE + (chunk & 1) * 4 * B_TILE_B;

#pragma unroll
        for (int q = 0; q < 4; q++) {
            int slot = tid + q * 256;
            int row = slot >> 3, k4 = (slot & 7) * 4;
            int gr = bm + row;
            float4 v = {0.f, 0.f, 0.f, 0.f};
            if (gr < M) v = *(const float4*)(A + (size_t)gr * K + k0 + k4);
            uint32_t h[2], l[2];
            split4(v, h, l);
            int si = row * 20 + (k4 >> 1);
            ((uint32_t*)(smem + OAH))[si] = h[0];
            ((uint32_t*)(smem + OAH))[si + 1] = h[1];
            ((uint32_t*)(smem + OAL))[si] = l[0];
            ((uint32_t*)(smem + OAL))[si + 1] = l[1];
        }

        if (chunk + 1 < nch) {
            int nbuf = OB_BASE + ((chunk + 1) & 1) * 4 * B_TILE_B;
            size_t ge = (size_t)(((chunk + 1) << 5) + brow) * N + bn + bseg * 8;
#pragma unroll
            for (int t = 0; t < 4; t++)
                CP_ASYNC16(sb + nbuf + t * B_TILE_B + bso, gB[t] + ge);
            CP_COMMIT();
            CP_WAIT(1);
        } else {
            CP_WAIT(0);
        }
        __syncthreads();

#pragma unroll
        for (int kk = 0; kk < 2; kk++) {
            uint32_t fah[2][4], fal[2][4];
#pragma unroll
            for (int mi = 0; mi < 2; mi++) {
                uint32_t aoff = (uint32_t)((wm * 32 + mi * 16 + (lane & 15)) * 80 +
                                           (lane >> 4) * 16 + kk * 32);
                LDSM_X4(fah[mi][0], fah[mi][1], fah[mi][2], fah[mi][3], sb + OAH + aoff);
                LDSM_X4(fal[mi][0], fal[mi][1], fal[mi][2], fal[mi][3], sb + OAL + aoff);
            }
            uint32_t fbsh[4][2], fbsl[4][2], fbth[4][2], fbtl[4][2];
#pragma unroll
            for (int np = 0; np < 2; np++) {
                int r = kk * 16 + (lane & 7) + ((lane >> 3) & 1) * 8;
                int cu = wn * 4 + np * 2 + (lane >> 4);
                uint32_t boff = (uint32_t)(r * 128 + ((cu ^ (r & 7)) << 4));
                LDSM_X4T(fbsh[2 * np][0], fbsh[2 * np][1], fbsh[2 * np + 1][0], fbsh[2 * np + 1][1], sb + obuf + 0 * B_TILE_B + boff);
                LDSM_X4T(fbsl[2 * np][0], fbsl[2 * np][1], fbsl[2 * np + 1][0], fbsl[2 * np + 1][1], sb + obuf + 1 * B_TILE_B + boff);
                LDSM_X4T(fbth[2 * np][0], fbth[2 * np][1], fbth[2 * np + 1][0], fbth[2 * np + 1][1], sb + obuf + 2 * B_TILE_B + boff);
                LDSM_X4T(fbtl[2 * np][0], fbtl[2 * np][1], fbtl[2 * np + 1][0], fbtl[2 * np + 1][1], sb + obuf + 3 * B_TILE_B + boff);
            }
#pragma unroll
            for (int mi = 0; mi < 2; mi++)
#pragma unroll
                for (int nj = 0; nj < 4; nj++) {
                    MMA_BF16(accS[mi][nj], fah[mi], fbsh[nj]);
                    MMA_BF16(accS[mi][nj], fah[mi], fbsl[nj]);
                    MMA_BF16(accS[mi][nj], fal[mi], fbsh[nj]);
                    MMA_BF16(accT[mi][nj], fah[mi], fbth[nj]);
                    MMA_BF16(accT[mi][nj], fah[mi], fbtl[nj]);
                    MMA_BF16(accT[mi][nj], fal[mi], fbth[nj]);
                }
        }
        __syncthreads();
    }

    int g = lane >> 2, c2 = (lane & 3) * 2;
#pragma unroll
    for (int mi = 0; mi < 2; mi++)
#pragma unroll
        for (int nj = 0; nj < 4; nj++) {
            int col = bn + wn * 32 + nj * 8 + c2;
            float2 bv = *(const float2*)(bias + col);
            int r0 = bm + wm * 32 + mi * 16 + g;
            if (r0 < M) {
                float2 os = {accS[mi][nj][0] + bv.x, accS[mi][nj][1] + bv.y};
                *(float2*)(S + (size_t)r0 * N + col) = os;
                ((uint32_t*)T)[((size_t)r0 * N + col) >> 1] =
                    bpack(__float2bfloat16_rn(accT[mi][nj][0]), __float2bfloat16_rn(accT[mi][nj][1]));
            }
            int r1 = r0 + 8;
            if (r1 < M) {
                float2 os = {accS[mi][nj][2] + bv.x, accS[mi][nj][3] + bv.y};
                *(float2*)(S + (size_t)r1 * N + col) = os;
                ((uint32_t*)T)[((size_t)r1 * N + col) >> 1] =
                    bpack(__float2bfloat16_rn(accT[mi][nj][2]), __float2bfloat16_rn(accT[mi][nj][3]));
            }
        }
}

// ---------------- fused layer-2 aggregation + node scores: half-warp, bf16 t2 ----------------
__global__ void k_agg2_scores(const float* __restrict__ Wp) {
    int halves_per_blk = blockDim.x >> 4;
    int n = blockIdx.x * halves_per_blk + (threadIdx.x >> 4);
    if (n >= N_NODES) return;
    int lane = threadIdx.x & 15;
    int beg = g_rowptr[n], end = g_rowptr[n + 1];

    float a0[8] = {0.f, 0.f, 0.f, 0.f, 0.f, 0.f, 0.f, 0.f};
    float a1[8] = {0.f, 0.f, 0.f, 0.f, 0.f, 0.f, 0.f, 0.f};
    int j = beg;
    for (; j + 1 < end; j += 2) {
        int s0 = g_csr_src[j];
        int s1 = g_csr_src[j + 1];
        uint4 v0 = __ldg(&((const uint4*)(g_t2b + (size_t)s0 * 128))[lane]);
        uint4 v1 = __ldg(&((const uint4*)(g_t2b + (size_t)s1 * 128))[lane]);
        acc_bf16x8(a0, v0);
        acc_bf16x8(a1, v1);
    }
    if (j < end) {
        int s0 = g_csr_src[j];
        uint4 v0 = __ldg(&((const uint4*)(g_t2b + (size_t)s0 * 128))[lane]);
        acc_bf16x8(a0, v0);
    }
#pragma unroll
    for (int q = 0; q < 8; q++) a0[q] += a1[q];

    int deg = end - beg;
    float inv = (deg > 0) ? 1.f / (float)deg : 0.f;
    const float4* srow = (const float4*)(g_s2 + (size_t)n * 128);
    float4 sv0 = srow[lane * 2], sv1 = srow[lane * 2 + 1];
    float h[8];
    h[0] = sv0.x + a0[0] * inv; h[1] = sv0.y + a0[1] * inv;
    h[2] = sv0.z + a0[2] * inv; h[3] = sv0.w + a0[3] * inv;
    h[4] = sv1.x + a0[4] * inv; h[5] = sv1.y + a0[5] * inv;
    h[6] = sv1.z + a0[6] * inv; h[7] = sv1.w + a0[7] * inv;

    const float4* wp4 = (const float4*)Wp;
    float4 wa0 = __ldg(&wp4[lane * 2]);
    float4 wa1 = __ldg(&wp4[lane * 2 + 1]);
    float4 wb0 = __ldg(&wp4[32 + lane * 2]);
    float4 wb1 = __ldg(&wp4[32 + lane * 2 + 1]);
    float a = h[0] * wa0.x + h[1] * wa0.y + h[2] * wa0.z + h[3] * wa0.w
            + h[4] * wa1.x + h[5] * wa1.y + h[6] * wa1.z + h[7] * wa1.w;
    float b = h[0] * wb0.x + h[1] * wb0.y + h[2] * wb0.z + h[3] * wb0.w
            + h[4] * wb1.x + h[5] * wb1.y + h[6] * wb1.z + h[7] * wb1.w;
#pragma unroll
    for (int off = 8; off; off >>= 1) {
        a += __shfl_down_sync(0xFFFFFFFFu, a, off, 16);
        b += __shfl_down_sync(0xFFFFFFFFu, b, off, 16);
    }
    if (lane == 0) { g_sA[n] = a; g_sB[n] = b; }
}

__global__ void k_edge_scores(const int* __restrict__ psrc, const int* __restrict__ pdst,
                              const int* __restrict__ nsrc, const int* __restrict__ ndst,
                              const float* __restrict__ bp, float* __restrict__ out,
                              int EP, int EN) {
    int i = blockIdx.x * blockDim.x + threadIdx.x;
    float b = bp[0];
    if (i < EP) {
        out[i] = g_sA[psrc[i]] + g_sB[pdst[i]] + b;
    } else if (i < EP + EN) {
        int j = i - EP;
        out[i] = g_sA[nsrc[j]] + g_sB[ndst[j]] + b;
    }
}

// ---------------- launch ----------------
extern "C" void kernel_launch(void* const* d_in, const int* in_sizes, int n_in,
                              void* d_out, int out_size) {
    const float* x    = (const float*)d_in[0];
    const int* msrc   = (const int*)d_in[1];
    const int* mdst   = (const int*)d_in[2];
    const int* psrc   = (const int*)d_in[3];
    const int* pdst   = (const int*)d_in[4];
    const int* nsrc   = (const int*)d_in[5];
    const int* ndst   = (const int*)d_in[6];
    const float* W1s  = (const float*)d_in[7];
    const float* W1n  = (const float*)d_in[8];
    const float* b1   = (const float*)d_in[9];
    const float* W2s  = (const float*)d_in[10];
    const float* W2n  = (const float*)d_in[11];
    const float* b2   = (const float*)d_in[12];
    const float* Wp   = (const float*)d_in[13];
    const float* bp   = (const float*)d_in[14];
    float* out = (float*)d_out;

    int E  = in_sizes[1];
    int EP = in_sizes[3];
    int EN = in_sizes[5];

    float *p_neigh1, *p_h1, *p_s2;
    __nv_bfloat16* p_t2b;
    cudaGetSymbolAddress((void**)&p_neigh1, g_neigh1);
    cudaGetSymbolAddress((void**)&p_h1,     g_h1);
    cudaGetSymbolAddress((void**)&p_s2,     g_s2);
    cudaGetSymbolAddress((void**)&p_t2b,    g_t2b);

    __nv_bfloat16 *w1sh, *w1sl, *w1nh, *w1nl, *w2sh, *w2sl, *w2nh, *w2nl;
    cudaGetSymbolAddress((void**)&w1sh, g_w1s_h);
    cudaGetSymbolAddress((void**)&w1sl, g_w1s_l);
    cudaGetSymbolAddress((void**)&w1nh, g_w1n_h);
    cudaGetSymbolAddress((void**)&w1nl, g_w1n_l);
    cudaGetSymbolAddress((void**)&w2sh, g_w2s_h);
    cudaGetSymbolAddress((void**)&w2sl, g_w2s_l);
    cudaGetSymbolAddress((void**)&w2nh, g_w2n_h);
    cudaGetSymbolAddress((void**)&w2nl, g_w2n_l);

    const int SMEM_DUAL = 4 * A_TILE_B + 2 * 4 * B_TILE_B;  // 73728
    const int SMEM_PAIR = 2 * A_TILE_B + 2 * 4 * B_TILE_B;  // 53248
    cudaFuncSetAttribute(k_mm_dual, cudaFuncAttributeMaxDynamicSharedMemorySize, SMEM_DUAL);
    cudaFuncSetAttribute(k_mm_pair, cudaFuncAttributeMaxDynamicSharedMemorySize, SMEM_PAIR);

    // prep (cnt zero + weight split + x->bf16), then CSR build (2-phase scan)
    k_prep_all<<<(XQ4 + 255) / 256, 256>>>(W1s, W1n, W2s, W2n, x);
    k_hist<<<(E + 255) / 256, 256>>>(mdst, E);
    k_scan1<<<NBLK_SCAN, 1024>>>();
    k_scan3<<<NBLK_SCAN, 1024>>>();
    k_fill<<<(E + 255) / 256, 256>>>(msrc, mdst, E);

    // layer 1 (bf16 gather -> fp32 neigh1)
    k_agg128<<<(N_NODES + 15) / 16, 256>>>(p_neigh1);
    {
        dim3 grid(D_HID / 64, (N_NODES + 127) / 128);
        k_mm_dual<<<grid, 256, SMEM_DUAL>>>(x, p_neigh1, w1sh, w1sl, w1nh, w1nl,
                                            b1, p_h1, N_NODES, D_HID, D_IN);
    }
    // layer 2: project then aggregate (t2 stored bf16)
    {
        dim3 grid(D_OUT / 64, (N_NODES + 127) / 128);
        k_mm_pair<<<grid, 256, SMEM_PAIR>>>(p_h1, w2sh, w2sl, w2nh, w2nl,
                                            b2, p_s2, p_t2b, N_NODES, D_OUT, D_HID);
    }
    k_agg2_scores<<<(N_NODES + 15) / 16, 256>>>(Wp);

    // edge scoring
    k_edge_scores<<<(EP + EN + 255) / 256, 256>>>(psrc, pdst, nsrc, ndst, bp, out, EP, EN);
}

// round 15
// speedup vs baseline: 1.0099x; 1.0099x over previous
#include <cuda_runtime.h>
#include <cuda_bf16.h>
#include <cstdint>

#define N_NODES 50000
#define MAX_E   800000
#define D_IN    128
#define D_HID   256
#define D_OUT   128
#define NBLK_SCAN ((N_NODES + 1023) / 1024)   // 49

// ---------------- scratch (static device globals; no allocation) ----------------
__device__ float g_neigh1[(size_t)N_NODES * D_IN];
__device__ float g_h1[(size_t)N_NODES * D_HID];
__device__ float g_s2[(size_t)N_NODES * D_OUT];
__device__ __nv_bfloat16 g_t2b[(size_t)N_NODES * D_OUT];   // t2 in bf16 (gather-only)
__device__ float g_sA[N_NODES];
__device__ float g_sB[N_NODES];
__device__ int   g_cnt[N_NODES];          // zero at load; self-zeroed by k_scan each run
__device__ int   g_rowptr[N_NODES + 1];
__device__ int   g_cursor[N_NODES];
__device__ int   g_csr_src[MAX_E];
__device__ unsigned long long g_lb[64];   // lookback state: (flag<<32)|value

// pre-split bf16 weights, same (K,N) layout as the fp32 originals
__device__ __nv_bfloat16 g_w1s_h[D_IN * D_HID], g_w1s_l[D_IN * D_HID];
__device__ __nv_bfloat16 g_w1n_h[D_IN * D_HID], g_w1n_l[D_IN * D_HID];
__device__ __nv_bfloat16 g_w2s_h[D_HID * D_OUT], g_w2s_l[D_HID * D_OUT];
__device__ __nv_bfloat16 g_w2n_h[D_HID * D_OUT], g_w2n_l[D_HID * D_OUT];

// ---------------- helpers ----------------
__device__ __forceinline__ uint32_t smem_u32(const void* p) {
    uint32_t a;
    asm("{ .reg .u64 t; cvta.to.shared.u64 t, %1; cvt.u32.u64 %0, t; }" : "=r"(a) : "l"(p));
    return a;
}
__device__ __forceinline__ uint32_t bpack(__nv_bfloat16 a, __nv_bfloat16 b) {
    return (uint32_t)__bfloat16_as_ushort(a) | ((uint32_t)__bfloat16_as_ushort(b) << 16);
}
__device__ __forceinline__ void split4(float4 v, uint32_t* h, uint32_t* l) {
    __nv_bfloat16 hx = __float2bfloat16_rn(v.x);
    __nv_bfloat16 hy = __float2bfloat16_rn(v.y);
    __nv_bfloat16 hz = __float2bfloat16_rn(v.z);
    __nv_bfloat16 hw = __float2bfloat16_rn(v.w);
    h[0] = bpack(hx, hy);
    h[1] = bpack(hz, hw);
    __nv_bfloat16 lx = __float2bfloat16_rn(v.x - __bfloat162float(hx));
    __nv_bfloat16 ly = __float2bfloat16_rn(v.y - __bfloat162float(hy));
    __nv_bfloat16 lz = __float2bfloat16_rn(v.z - __bfloat162float(hz));
    __nv_bfloat16 lw = __float2bfloat16_rn(v.w - __bfloat162float(hw));
    l[0] = bpack(lx, ly);
    l[1] = bpack(lz, lw);
}
__device__ __forceinline__ void acc_bf16x8(float* acc, uint4 v) {
    float2 f;
    f = __bfloat1622float2(*(__nv_bfloat162*)&v.x); acc[0] += f.x; acc[1] += f.y;
    f = __bfloat1622float2(*(__nv_bfloat162*)&v.y); acc[2] += f.x; acc[3] += f.y;
    f = __bfloat1622float2(*(__nv_bfloat162*)&v.z); acc[4] += f.x; acc[5] += f.y;
    f = __bfloat1622float2(*(__nv_bfloat162*)&v.w); acc[6] += f.x; acc[7] += f.y;
}

#define LDSM_X4(r0, r1, r2, r3, addr) \
    asm volatile("ldmatrix.sync.aligned.m8n8.x4.shared.b16 {%0,%1,%2,%3}, [%4];" \
                 : "=r"(r0), "=r"(r1), "=r"(r2), "=r"(r3) : "r"(addr))
#define LDSM_X4T(r0, r1, r2, r3, addr) \
    asm volatile("ldmatrix.sync.aligned.m8n8.x4.trans.shared.b16 {%0,%1,%2,%3}, [%4];" \
                 : "=r"(r0), "=r"(r1), "=r"(r2), "=r"(r3) : "r"(addr))
#define MMA_BF16(c, a, b) \
    asm volatile("mma.sync.aligned.m16n8k16.row.col.f32.bf16.bf16.f32 " \
                 "{%0,%1,%2,%3}, {%4,%5,%6,%7}, {%8,%9}, {%0,%1,%2,%3};" \
                 : "+f"((c)[0]), "+f"((c)[1]), "+f"((c)[2]), "+f"((c)[3]) \
                 : "r"((a)[0]), "r"((a)[1]), "r"((a)[2]), "r"((a)[3]), \
                   "r"((b)[0]), "r"((b)[1]))
#define CP_ASYNC16(saddr, gptr) \
    asm volatile("cp.async.cg.shared.global [%0], [%1], 16;" :: "r"(saddr), "l"(gptr))
#define CP_COMMIT() asm volatile("cp.async.commit_group;")
#define CP_WAIT(n)  asm volatile("cp.async.wait_group %0;" :: "n"(n))

// ---------------- merged prep + hist: weight split, lookback reset, histogram ----------------
__global__ void k_prep_hist(
    const float* __restrict__ W1s, const float* __restrict__ W1n,
    const float* __restrict__ W2s, const float* __restrict__ W2n,
    const int* __restrict__ dst, int E)
{
    int i = blockIdx.x * blockDim.x + threadIdx.x;
    if (i < 64) g_lb[i] = 0ull;
    if (i < 4 * 32768) {
        int a = i >> 15, r = i & 32767;
        const float* W = (a == 0) ? W1s : (a == 1) ? W1n : (a == 2) ? W2s : W2n;
        __nv_bfloat16* hi = (a == 0) ? g_w1s_h : (a == 1) ? g_w1n_h : (a == 2) ? g_w2s_h : g_w2n_h;
        __nv_bfloat16* lo = (a == 0) ? g_w1s_l : (a == 1) ? g_w1n_l : (a == 2) ? g_w2s_l : g_w2n_l;
        float w = W[r];
        __nv_bfloat16 h = __float2bfloat16_rn(w);
        hi[r] = h;
        lo[r] = __float2bfloat16_rn(w - __bfloat162float(h));
    }
    if (i < E) atomicAdd(&g_cnt[dst[i]], 1);
}

// ---------------- single-pass scan with decoupled lookback ----------------
// g_cnt -> exclusive prefix (rowptr/cursor); self-zeroes g_cnt for next replay.
__global__ void k_scan() {
    __shared__ int wscan[32];
    __shared__ int s_prefix;
    int t = threadIdx.x, lane = t & 31, w = t >> 5;
    int b = blockIdx.x;
    int idx = b * 1024 + t;

    int v = (idx < N_NODES) ? g_cnt[idx] : 0;
    if (idx < N_NODES) g_cnt[idx] = 0;     // reset for next execution

    int iv = v;
#pragma unroll
    for (int off = 1; off < 32; off <<= 1) {
        int u = __shfl_up_sync(0xFFFFFFFFu, iv, off);
        if (lane >= off) iv += u;
    }
    if (lane == 31) wscan[w] = iv;
    __syncthreads();
    if (w == 0) {
        int s = wscan[lane];
#pragma unroll
        for (int off = 1; off < 32; off <<= 1) {
            int u = __shfl_up_sync(0xFFFFFFFFu, s, off);
            if (lane >= off) s += u;
        }
        wscan[lane] = s;
    }
    __syncthreads();
    int warp_off = (w == 0) ? 0 : wscan[w - 1];
    int tot = wscan[31];

    if (t == 0) {
        if (b == 0) {
            s_prefix = 0;
            atomicExch(&g_lb[0], (2ull << 32) | (unsigned int)tot);
        } else {
            atomicExch(&g_lb[b], (1ull << 32) | (unsigned int)tot);
            int run = 0;
            int j = b - 1;
            for (;;) {
                unsigned long long e;
                do { e = *(volatile unsigned long long*)&g_lb[j]; } while ((e >> 32) == 0ull);
                run += (int)(unsigned int)e;
                if ((e >> 32) == 2ull) break;
                j--;
            }
            s_prefix = run;
            atomicExch(&g_lb[b], (2ull << 32) | (unsigned int)(run + tot));
            if (b == NBLK_SCAN - 1) g_rowptr[N_NODES] = run + tot;
        }
    }
    __syncthreads();
    if (idx < N_NODES) {
        int ex = iv - v + warp_off + s_prefix;
        g_rowptr[idx] = ex;
        g_cursor[idx] = ex;
    }
}

__global__ void k_fill(const int* __restrict__ src, const int* __restrict__ dst, int E) {
    int e = blockIdx.x * blockDim.x + threadIdx.x;
    if (e < E) {
        int d = dst[e];
        int pos = atomicAdd(&g_cursor[d], 1);
        g_csr_src[pos] = src[e];
    }
}

// ---------------- layer-1 aggregation: half-warp per node, fp32 gather (round-13 proven) ----------------
__global__ void k_agg128(const float* __restrict__ feat, float* __restrict__ out) {
    int halves_per_blk = blockDim.x >> 4;
    int n = blockIdx.x * halves_per_blk + (threadIdx.x >> 4);
    if (n >= N_NODES) return;
    int lane = threadIdx.x & 15;
    int beg = g_rowptr[n], end = g_rowptr[n + 1];

    float4 aA0 = {0.f, 0.f, 0.f, 0.f}, aB0 = {0.f, 0.f, 0.f, 0.f};
    float4 aA1 = {0.f, 0.f, 0.f, 0.f}, aB1 = {0.f, 0.f, 0.f, 0.f};
    int j = beg;
    for (; j + 1 < end; j += 2) {
        int s0 = g_csr_src[j];
        int s1 = g_csr_src[j + 1];
        const float4* r0 = (const float4*)(feat + (size_t)s0 * 128);
        const float4* r1 = (const float4*)(feat + (size_t)s1 * 128);
        float4 vA0 = __ldg(&r0[lane]);
        float4 vB0 = __ldg(&r0[lane + 16]);
        float4 vA1 = __ldg(&r1[lane]);
        float4 vB1 = __ldg(&r1[lane + 16]);
        aA0.x += vA0.x; aA0.y += vA0.y; aA0.z += vA0.z; aA0.w += vA0.w;
        aB0.x += vB0.x; aB0.y += vB0.y; aB0.z += vB0.z; aB0.w += vB0.w;
        aA1.x += vA1.x; aA1.y += vA1.y; aA1.z += vA1.z; aA1.w += vA1.w;
        aB1.x += vB1.x; aB1.y += vB1.y; aB1.z += vB1.z; aB1.w += vB1.w;
    }
    if (j < end) {
        int s0 = g_csr_src[j];
        const float4* r0 = (const float4*)(feat + (size_t)s0 * 128);
        float4 vA0 = __ldg(&r0[lane]);
        float4 vB0 = __ldg(&r0[lane + 16]);
        aA0.x += vA0.x; aA0.y += vA0.y; aA0.z += vA0.z; aA0.w += vA0.w;
        aB0.x += vB0.x; aB0.y += vB0.y; aB0.z += vB0.z; aB0.w += vB0.w;
    }
    aA0.x += aA1.x; aA0.y += aA1.y; aA0.z += aA1.z; aA0.w += aA1.w;
    aB0.x += aB1.x; aB0.y += aB1.y; aB0.z += aB1.z; aB0.w += aB1.w;
    int deg = end - beg;
    float inv = (deg > 0) ? 1.f / (float)deg : 0.f;
    float4* orow = (float4*)(out + (size_t)n * 128);
    float4 oA = {aA0.x * inv, aA0.y * inv, aA0.z * inv, aA0.w * inv};
    float4 oB = {aB0.x * inv, aB0.y * inv, aB0.z * inv, aB0.w * inv};
    orow[lane] = oA;
    orow[lane + 16] = oB;
}

// ================= bf16x3 mma.sync GEMMs: swizzled-B double-buffer =================
#define A_TILE_B 10240
#define B_TILE_B 4096

// -------- layer 1: C = relu(A1@B1 + A2@B2 + bias) --------
__global__ void __launch_bounds__(256) k_mm_dual(
    const float* __restrict__ A1, const float* __restrict__ A2,
    const __nv_bfloat16* __restrict__ B1h, const __nv_bfloat16* __restrict__ B1l,
    const __nv_bfloat16* __restrict__ B2h, const __nv_bfloat16* __restrict__ B2l,
    const float* __restrict__ bias, float* __restrict__ C,
    int M, int N, int K)
{
    extern __shared__ char smem[];
    const int OA1H = 0, OA1L = A_TILE_B, OA2H = 2 * A_TILE_B, OA2L = 3 * A_TILE_B;
    const int OB_BASE = 4 * A_TILE_B;
    uint32_t sb = smem_u32(smem);

    int tid = threadIdx.x, lane = tid & 31, wid = tid >> 5;
    int wm = wid & 3, wn = wid >> 2;
    int bm = blockIdx.y * 128, bn = blockIdx.x * 64;
    const int nch = K >> 5;

    int brow = tid >> 3, bseg = tid & 7;
    uint32_t bso = (uint32_t)(brow * 128 + ((bseg ^ (brow & 7)) << 4));
    const __nv_bfloat16* gB[4] = {B1h, B1l, B2h, B2l};

    float acc[2][4][4];
#pragma unroll
    for (int i = 0; i < 2; i++)
#pragma unroll
        for (int j = 0; j < 4; j++)
#pragma unroll
            for (int q = 0; q < 4; q++) acc[i][j][q] = 0.f;

    {
        size_t ge = (size_t)brow * N + bn + bseg * 8;
#pragma unroll
        for (int t = 0; t < 4; t++)
            CP_ASYNC16(sb + OB_BASE + t * B_TILE_B + bso, gB[t] + ge);
        CP_COMMIT();
    }

    for (int chunk = 0; chunk < nch; chunk++) {
        int k0 = chunk << 5;
        int obuf = OB_BASE + (chunk & 1) * 4 * B_TILE_B;

#pragma unroll
        for (int q = 0; q < 4; q++) {
            int slot = tid + q * 256;
            int row = slot >> 3, k4 = (slot & 7) * 4;
            int gr = bm + row;
            float4 v1 = {0.f, 0.f, 0.f, 0.f}, v2 = {0.f, 0.f, 0.f, 0.f};
            if (gr < M) {
                v1 = *(const float4*)(A1 + (size_t)gr * K + k0 + k4);
                v2 = *(const float4*)(A2 + (size_t)gr * K + k0 + k4);
            }
            uint32_t h[2], l[2];
            int si = row * 20 + (k4 >> 1);
            split4(v1, h, l);
            ((uint32_t*)(smem + OA1H))[si] = h[0];
            ((uint32_t*)(smem + OA1H))[si + 1] = h[1];
            ((uint32_t*)(smem + OA1L))[si] = l[0];
            ((uint32_t*)(smem + OA1L))[si + 1] = l[1];
            split4(v2, h, l);
            ((uint32_t*)(smem + OA2H))[si] = h[0];
            ((uint32_t*)(smem + OA2H))[si + 1] = h[1];
            ((uint32_t*)(smem + OA2L))[si] = l[0];
            ((uint32_t*)(smem + OA2L))[si + 1] = l[1];
        }

        if (chunk + 1 < nch) {
            int nbuf = OB_BASE + ((chunk + 1) & 1) * 4 * B_TILE_B;
            size_t ge = (size_t)(((chunk + 1) << 5) + brow) * N + bn + bseg * 8;
#pragma unroll
            for (int t = 0; t < 4; t++)
                CP_ASYNC16(sb + nbuf + t * B_TILE_B + bso, gB[t] + ge);
            CP_COMMIT();
            CP_WAIT(1);
        } else {
            CP_WAIT(0);
        }
        __syncthreads();

#pragma unroll
        for (int kk = 0; kk < 2; kk++) {
            uint32_t fa1h[2][4], fa1l[2][4], fa2h[2][4], fa2l[2][4];
#pragma unroll
            for (int mi = 0; mi < 2; mi++) {
                uint32_t aoff = (uint32_t)((wm * 32 + mi * 16 + (lane & 15)) * 80 +
                                           (lane >> 4) * 16 + kk * 32);
                LDSM_X4(fa1h[mi][0], fa1h[mi][1], fa1h[mi][2], fa1h[mi][3], sb + OA1H + aoff);
                LDSM_X4(fa1l[mi][0], fa1l[mi][1], fa1l[mi][2], fa1l[mi][3], sb + OA1L + aoff);
                LDSM_X4(fa2h[mi][0], fa2h[mi][1], fa2h[mi][2], fa2h[mi][3], sb + OA2H + aoff);
                LDSM_X4(fa2l[mi][0], fa2l[mi][1], fa2l[mi][2], fa2l[mi][3], sb + OA2L + aoff);
            }
            uint32_t fb1h[4][2], fb1l[4][2], fb2h[4][2], fb2l[4][2];
#pragma unroll
            for (int np = 0; np < 2; np++) {
                int r = kk * 16 + (lane & 7) + ((lane >> 3) & 1) * 8;
                int cu = wn * 4 + np * 2 + (lane >> 4);
                uint32_t boff = (uint32_t)(r * 128 + ((cu ^ (r & 7)) << 4));
                LDSM_X4T(fb1h[2 * np][0], fb1h[2 * np][1], fb1h[2 * np + 1][0], fb1h[2 * np + 1][1], sb + obuf + 0 * B_TILE_B + boff);
                LDSM_X4T(fb1l[2 * np][0], fb1l[2 * np][1], fb1l[2 * np + 1][0], fb1l[2 * np + 1][1], sb + obuf + 1 * B_TILE_B + boff);
                LDSM_X4T(fb2h[2 * np][0], fb2h[2 * np][1], fb2h[2 * np + 1][0], fb2h[2 * np + 1][1], sb + obuf + 2 * B_TILE_B + boff);
                LDSM_X4T(fb2l[2 * np][0], fb2l[2 * np][1], fb2l[2 * np + 1][0], fb2l[2 * np + 1][1], sb + obuf + 3 * B_TILE_B + boff);
            }
#pragma unroll
            for (int mi = 0; mi < 2; mi++)
#pragma unroll
                for (int nj = 0; nj < 4; nj++) {
                    MMA_BF16(acc[mi][nj], fa1h[mi], fb1h[nj]);
                    MMA_BF16(acc[mi][nj], fa1h[mi], fb1l[nj]);
                    MMA_BF16(acc[mi][nj], fa1l[mi], fb1h[nj]);
                    MMA_BF16(acc[mi][nj], fa2h[mi], fb2h[nj]);
                    MMA_BF16(acc[mi][nj], fa2h[mi], fb2l[nj]);
                    MMA_BF16(acc[mi][nj], fa2l[mi], fb2h[nj]);
                }
        }
        __syncthreads();
    }

    int g = lane >> 2, c2 = (lane & 3) * 2;
#pragma unroll
    for (int mi = 0; mi < 2; mi++)
#pragma unroll
        for (int nj = 0; nj < 4; nj++) {
            int col = bn + wn * 32 + nj * 8 + c2;
            float2 bv = *(const float2*)(bias + col);
            int r0 = bm + wm * 32 + mi * 16 + g;
            if (r0 < M) {
                float2 o;
                o.x = fmaxf(acc[mi][nj][0] + bv.x, 0.f);
                o.y = fmaxf(acc[mi][nj][1] + bv.y, 0.f);
                *(float2*)(C + (size_t)r0 * N + col) = o;
            }
            int r1 = r0 + 8;
            if (r1 < M) {
                float2 o;
                o.x = fmaxf(acc[mi][nj][2] + bv.x, 0.f);
                o.y = fmaxf(acc[mi][nj][3] + bv.y, 0.f);
                *(float2*)(C + (size_t)r1 * N + col) = o;
            }
        }
}

// -------- layer 2: S = A@Bs + bias (fp32), T = A@Bt (bf16) --------
__global__ void __launch_bounds__(256) k_mm_pair(
    const float* __restrict__ A,
    const __nv_bfloat16* __restrict__ Bsh, const __nv_bfloat16* __restrict__ Bsl,
    const __nv_bfloat16* __restrict__ Bth, const __nv_bfloat16* __restrict__ Btl,
    const float* __restrict__ bias, float* __restrict__ S, __nv_bfloat16* __restrict__ T,
    int M, int N, int K)
{
    extern __shared__ char smem[];
    const int OAH = 0, OAL = A_TILE_B;
    const int OB_BASE = 2 * A_TILE_B;
    uint32_t sb = smem_u32(smem);

    int tid = threadIdx.x, lane = tid & 31, wid = tid >> 5;
    int wm = wid & 3, wn = wid >> 2;
    int bm = blockIdx.y * 128, bn = blockIdx.x * 64;
    const int nch = K >> 5;

    int brow = tid >> 3, bseg = tid & 7;
    uint32_t bso = (uint32_t)(brow * 128 + ((bseg ^ (brow & 7)) << 4));
    const __nv_bfloat16* gB[4] = {Bsh, Bsl, Bth, Btl};

    float accS[2][4][4], accT[2][4][4];
#pragma unroll
    for (int i = 0; i < 2; i++)
#pragma unroll
        for (int j = 0; j < 4; j++)
#pragma unroll
            for (int q = 0; q < 4; q++) { accS[i][j][q] = 0.f; accT[i][j][q] = 0.f; }

    {
        size_t ge = (size_t)brow * N + bn + bseg * 8;
#pragma unroll
        for (int t = 0; t < 4; t++)
            CP_ASYNC16(sb + OB_BASE + t * B_TILE_B + bso, gB[t] + ge);
        CP_COMMIT();
    }

    for (int chunk = 0; chunk < nch; chunk++) {
        int k0 = chunk << 5;
        int obuf = OB_BASE + (chunk & 1) * 4 * B_TILE_B;

#pragma unroll
        for (int q = 0; q < 4; q++) {
            int slot = tid + q * 256;
            int row = slot >> 3, k4 = (slot & 7) * 4;
            int gr = bm + row;
            float4 v = {0.f, 0.f, 0.f, 0.f};
            if (gr < M) v = *(const float4*)(A + (size_t)gr * K + k0 + k4);
            uint32_t h[2], l[2];
            split4(v, h, l);
            int si = row * 20 + (k4 >> 1);
            ((uint32_t*)(smem + OAH))[si] = h[0];
            ((uint32_t*)(smem + OAH))[si + 1] = h[1];
            ((uint32_t*)(smem + OAL))[si] = l[0];
            ((uint32_t*)(smem + OAL))[si + 1] = l[1];
        }

        if (chunk + 1 < nch) {
            int nbuf = OB_BASE + ((chunk + 1) & 1) * 4 * B_TILE_B;
            size_t ge = (size_t)(((chunk + 1) << 5) + brow) * N + bn + bseg * 8;
#pragma unroll
            for (int t = 0; t < 4; t++)
                CP_ASYNC16(sb + nbuf + t * B_TILE_B + bso, gB[t] + ge);
            CP_COMMIT();
            CP_WAIT(1);
        } else {
            CP_WAIT(0);
        }
        __syncthreads();

#pragma unroll
        for (int kk = 0; kk < 2; kk++) {
            uint32_t fah[2][4], fal[2][4];
#pragma unroll
            for (int mi = 0; mi < 2; mi++) {
                uint32_t aoff = (uint32_t)((wm * 32 + mi * 16 + (lane & 15)) * 80 +
                                           (lane >> 4) * 16 + kk * 32);
                LDSM_X4(fah[mi][0], fah[mi][1], fah[mi][2], fah[mi][3], sb + OAH + aoff);
                LDSM_X4(fal[mi][0], fal[mi][1], fal[mi][2], fal[mi][3], sb + OAL + aoff);
            }
            uint32_t fbsh[4][2], fbsl[4][2], fbth[4][2], fbtl[4][2];
#pragma unroll
            for (int np = 0; np < 2; np++) {
                int r = kk * 16 + (lane & 7) + ((lane >> 3) & 1) * 8;
                int cu = wn * 4 + np * 2 + (lane >> 4);
                uint32_t boff = (uint32_t)(r * 128 + ((cu ^ (r & 7)) << 4));
                LDSM_X4T(fbsh[2 * np][0], fbsh[2 * np][1], fbsh[2 * np + 1][0], fbsh[2 * np + 1][1], sb + obuf + 0 * B_TILE_B + boff);
                LDSM_X4T(fbsl[2 * np][0], fbsl[2 * np][1], fbsl[2 * np + 1][0], fbsl[2 * np + 1][1], sb + obuf + 1 * B_TILE_B + boff);
                LDSM_X4T(fbth[2 * np][0], fbth[2 * np][1], fbth[2 * np + 1][0], fbth[2 * np + 1][1], sb + obuf + 2 * B_TILE_B + boff);
                LDSM_X4T(fbtl[2 * np][0], fbtl[2 * np][1], fbtl[2 * np + 1][0], fbtl[2 * np + 1][1], sb + obuf + 3 * B_TILE_B + boff);
            }
#pragma unroll
            for (int mi = 0; mi < 2; mi++)
#pragma unroll
                for (int nj = 0; nj < 4; nj++) {
                    MMA_BF16(accS[mi][nj], fah[mi], fbsh[nj]);
                    MMA_BF16(accS[mi][nj], fah[mi], fbsl[nj]);
                    MMA_BF16(accS[mi][nj], fal[mi], fbsh[nj]);
                    MMA_BF16(accT[mi][nj], fah[mi], fbth[nj]);
                    MMA_BF16(accT[mi][nj], fah[mi], fbtl[nj]);
                    MMA_BF16(accT[mi][nj], fal[mi], fbth[nj]);
                }
        }
        __syncthreads();
    }

    int g = lane >> 2, c2 = (lane & 3) * 2;
#pragma unroll
    for (int mi = 0; mi < 2; mi++)
#pragma unroll
        for (int nj = 0; nj < 4; nj++) {
            int col = bn + wn * 32 + nj * 8 + c2;
            float2 bv = *(const float2*)(bias + col);
            int r0 = bm + wm * 32 + mi * 16 + g;
            if (r0 < M) {
                float2 os = {accS[mi][nj][0] + bv.x, accS[mi][nj][1] + bv.y};
                *(float2*)(S + (size_t)r0 * N + col) = os;
                ((uint32_t*)T)[((size_t)r0 * N + col) >> 1] =
                    bpack(__float2bfloat16_rn(accT[mi][nj][0]), __float2bfloat16_rn(accT[mi][nj][1]));
            }
            int r1 = r0 + 8;
            if (r1 < M) {
                float2 os = {accS[mi][nj][2] + bv.x, accS[mi][nj][3] + bv.y};
                *(float2*)(S + (size_t)r1 * N + col) = os;
                ((uint32_t*)T)[((size_t)r1 * N + col) >> 1] =
                    bpack(__float2bfloat16_rn(accT[mi][nj][2]), __float2bfloat16_rn(accT[mi][nj][3]));
            }
        }
}

// ---------------- fused layer-2 aggregation + node scores: half-warp, bf16 t2 ----------------
__global__ void k_agg2_scores(const float* __restrict__ Wp) {
    int halves_per_blk = blockDim.x >> 4;
    int n = blockIdx.x * halves_per_blk + (threadIdx.x >> 4);
    if (n >= N_NODES) return;
    int lane = threadIdx.x & 15;
    int beg = g_rowptr[n], end = g_rowptr[n + 1];

    float a0[8] = {0.f, 0.f, 0.f, 0.f, 0.f, 0.f, 0.f, 0.f};
    float a1[8] = {0.f, 0.f, 0.f, 0.f, 0.f, 0.f, 0.f, 0.f};
    int j = beg;
    for (; j + 1 < end; j += 2) {
        int s0 = g_csr_src[j];
        int s1 = g_csr_src[j + 1];
        uint4 v0 = __ldg(&((const uint4*)(g_t2b + (size_t)s0 * 128))[lane]);
        uint4 v1 = __ldg(&((const uint4*)(g_t2b + (size_t)s1 * 128))[lane]);
        acc_bf16x8(a0, v0);
        acc_bf16x8(a1, v1);
    }
    if (j < end) {
        int s0 = g_csr_src[j];
        uint4 v0 = __ldg(&((const uint4*)(g_t2b + (size_t)s0 * 128))[lane]);
        acc_bf16x8(a0, v0);
    }
#pragma unroll
    for (int q = 0; q < 8; q++) a0[q] += a1[q];

    int deg = end - beg;
    float inv = (deg > 0) ? 1.f / (float)deg : 0.f;
    const float4* srow = (const float4*)(g_s2 + (size_t)n * 128);
    float4 sv0 = srow[lane * 2], sv1 = srow[lane * 2 + 1];
    float h[8];
    h[0] = sv0.x + a0[0] * inv; h[1] = sv0.y + a0[1] * inv;
    h[2] = sv0.z + a0[2] * inv; h[3] = sv0.w + a0[3] * inv;
    h[4] = sv1.x + a0[4] * inv; h[5] = sv1.y + a0[5] * inv;
    h[6] = sv1.z + a0[6] * inv; h[7] = sv1.w + a0[7] * inv;

    const float4* wp4 = (const float4*)Wp;
    float4 wa0 = __ldg(&wp4[lane * 2]);
    float4 wa1 = __ldg(&wp4[lane * 2 + 1]);
    float4 wb0 = __ldg(&wp4[32 + lane * 2]);
    float4 wb1 = __ldg(&wp4[32 + lane * 2 + 1]);
    float a = h[0] * wa0.x + h[1] * wa0.y + h[2] * wa0.z + h[3] * wa0.w
            + h[4] * wa1.x + h[5] * wa1.y + h[6] * wa1.z + h[7] * wa1.w;
    float b = h[0] * wb0.x + h[1] * wb0.y + h[2] * wb0.z + h[3] * wb0.w
            + h[4] * wb1.x + h[5] * wb1.y + h[6] * wb1.z + h[7] * wb1.w;
#pragma unroll
    for (int off = 8; off; off >>= 1) {
        a += __shfl_down_sync(0xFFFFFFFFu, a, off, 16);
        b += __shfl_down_sync(0xFFFFFFFFu, b, off, 16);
    }
    if (lane == 0) { g_sA[n] = a; g_sB[n] = b; }
}

__global__ void k_edge_scores(const int* __restrict__ psrc, const int* __restrict__ pdst,
                              const int* __restrict__ nsrc, const int* __restrict__ ndst,
                              const float* __restrict__ bp, float* __restrict__ out,
                              int EP, int EN) {
    int i = blockIdx.x * blockDim.x + threadIdx.x;
    float b = bp[0];
    if (i < EP) {
        out[i] = g_sA[psrc[i]] + g_sB[pdst[i]] + b;
    } else if (i < EP + EN) {
        int j = i - EP;
        out[i] = g_sA[nsrc[j]] + g_sB[ndst[j]] + b;
    }
}

// ---------------- launch ----------------
extern "C" void kernel_launch(void* const* d_in, const int* in_sizes, int n_in,
                              void* d_out, int out_size) {
    const float* x    = (const float*)d_in[0];
    const int* msrc   = (const int*)d_in[1];
    const int* mdst   = (const int*)d_in[2];
    const int* psrc   = (const int*)d_in[3];
    const int* pdst   = (const int*)d_in[4];
    const int* nsrc   = (const int*)d_in[5];
    const int* ndst   = (const int*)d_in[6];
    const float* W1s  = (const float*)d_in[7];
    const float* W1n  = (const float*)d_in[8];
    const float* b1   = (const float*)d_in[9];
    const float* W2s  = (const float*)d_in[10];
    const float* W2n  = (const float*)d_in[11];
    const float* b2   = (const float*)d_in[12];
    const float* Wp   = (const float*)d_in[13];
    const float* bp   = (const float*)d_in[14];
    float* out = (float*)d_out;

    int E  = in_sizes[1];
    int EP = in_sizes[3];
    int EN = in_sizes[5];

    float *p_neigh1, *p_h1, *p_s2;
    __nv_bfloat16* p_t2b;
    cudaGetSymbolAddress((void**)&p_neigh1, g_neigh1);
    cudaGetSymbolAddress((void**)&p_h1,     g_h1);
    cudaGetSymbolAddress((void**)&p_s2,     g_s2);
    cudaGetSymbolAddress((void**)&p_t2b,    g_t2b);

    __nv_bfloat16 *w1sh, *w1sl, *w1nh, *w1nl, *w2sh, *w2sl, *w2nh, *w2nl;
    cudaGetSymbolAddress((void**)&w1sh, g_w1s_h);
    cudaGetSymbolAddress((void**)&w1sl, g_w1s_l);
    cudaGetSymbolAddress((void**)&w1nh, g_w1n_h);
    cudaGetSymbolAddress((void**)&w1nl, g_w1n_l);
    cudaGetSymbolAddress((void**)&w2sh, g_w2s_h);
    cudaGetSymbolAddress((void**)&w2sl, g_w2s_l);
    cudaGetSymbolAddress((void**)&w2nh, g_w2n_h);
    cudaGetSymbolAddress((void**)&w2nl, g_w2n_l);

    const int SMEM_DUAL = 4 * A_TILE_B + 2 * 4 * B_TILE_B;  // 73728
    const int SMEM_PAIR = 2 * A_TILE_B + 2 * 4 * B_TILE_B;  // 53248
    cudaFuncSetAttribute(k_mm_dual, cudaFuncAttributeMaxDynamicSharedMemorySize, SMEM_DUAL);
    cudaFuncSetAttribute(k_mm_pair, cudaFuncAttributeMaxDynamicSharedMemorySize, SMEM_PAIR);

    // merged prep+hist, single-pass lookback scan, fill
    k_prep_hist<<<(E + 255) / 256, 256>>>(W1s, W1n, W2s, W2n, mdst, E);
    k_scan<<<NBLK_SCAN, 1024>>>();
    k_fill<<<(E + 255) / 256, 256>>>(msrc, mdst, E);

    // layer 1
    k_agg128<<<(N_NODES + 15) / 16, 256>>>(x, p_neigh1);
    {
        dim3 grid(D_HID / 64, (N_NODES + 127) / 128);
        k_mm_dual<<<grid, 256, SMEM_DUAL>>>(x, p_neigh1, w1sh, w1sl, w1nh, w1nl,
                                            b1, p_h1, N_NODES, D_HID, D_IN);
    }
    // layer 2: project then aggregate (t2 stored bf16)
    {
        dim3 grid(D_OUT / 64, (N_NODES + 127) / 128);
        k_mm_pair<<<grid, 256, SMEM_PAIR>>>(p_h1, w2sh, w2sl, w2nh, w2nl,
                                            b2, p_s2, p_t2b, N_NODES, D_OUT, D_HID);
    }
    k_agg2_scores<<<(N_NODES + 15) / 16, 256>>>(Wp);

    // edge scoring
    k_edge_scores<<<(EP + EN + 255) / 256, 256>>>(psrc, pdst, nsrc, ndst, bp, out, EP, EN);
}

// round 16
// speedup vs baseline: 1.0210x; 1.0110x over previous
#include <cuda_runtime.h>
#include <cuda_bf16.h>
#include <cstdint>

#define N_NODES 50000
#define MAX_E   800000
#define D_IN    128
#define D_HID   256
#define D_OUT   128
#define NBLK_SCAN ((N_NODES + 1023) / 1024)   // 49

// ---------------- scratch (static device globals; no allocation) ----------------
__device__ float g_neigh1[(size_t)N_NODES * D_IN];
__device__ float g_h1[(size_t)N_NODES * D_HID];
__device__ float g_s2[(size_t)N_NODES * D_OUT];
__device__ __nv_bfloat16 g_t2b[(size_t)N_NODES * D_OUT];   // t2 in bf16 (gather-only)
__device__ float g_sA[N_NODES];
__device__ float g_sB[N_NODES];
__device__ int   g_cnt[N_NODES];          // zero at load; self-zeroed by k_scan each run
__device__ int   g_rowptr[N_NODES + 1];
__device__ int   g_rank[MAX_E];           // per-edge rank within its dst bucket
__device__ int   g_csr_src[MAX_E];
__device__ unsigned long long g_lb[64];   // lookback state: (flag<<32)|value

// pre-split bf16 weights, same (K,N) layout as the fp32 originals
__device__ __nv_bfloat16 g_w1s_h[D_IN * D_HID], g_w1s_l[D_IN * D_HID];
__device__ __nv_bfloat16 g_w1n_h[D_IN * D_HID], g_w1n_l[D_IN * D_HID];
__device__ __nv_bfloat16 g_w2s_h[D_HID * D_OUT], g_w2s_l[D_HID * D_OUT];
__device__ __nv_bfloat16 g_w2n_h[D_HID * D_OUT], g_w2n_l[D_HID * D_OUT];

// ---------------- helpers ----------------
__device__ __forceinline__ uint32_t smem_u32(const void* p) {
    uint32_t a;
    asm("{ .reg .u64 t; cvta.to.shared.u64 t, %1; cvt.u32.u64 %0, t; }" : "=r"(a) : "l"(p));
    return a;
}
__device__ __forceinline__ uint32_t bpack(__nv_bfloat16 a, __nv_bfloat16 b) {
    return (uint32_t)__bfloat16_as_ushort(a) | ((uint32_t)__bfloat16_as_ushort(b) << 16);
}
__device__ __forceinline__ void split4(float4 v, uint32_t* h, uint32_t* l) {
    __nv_bfloat16 hx = __float2bfloat16_rn(v.x);
    __nv_bfloat16 hy = __float2bfloat16_rn(v.y);
    __nv_bfloat16 hz = __float2bfloat16_rn(v.z);
    __nv_bfloat16 hw = __float2bfloat16_rn(v.w);
    h[0] = bpack(hx, hy);
    h[1] = bpack(hz, hw);
    __nv_bfloat16 lx = __float2bfloat16_rn(v.x - __bfloat162float(hx));
    __nv_bfloat16 ly = __float2bfloat16_rn(v.y - __bfloat162float(hy));
    __nv_bfloat16 lz = __float2bfloat16_rn(v.z - __bfloat162float(hz));
    __nv_bfloat16 lw = __float2bfloat16_rn(v.w - __bfloat162float(hw));
    l[0] = bpack(lx, ly);
    l[1] = bpack(lz, lw);
}
__device__ __forceinline__ void acc_bf16x8(float* acc, uint4 v) {
    float2 f;
    f = __bfloat1622float2(*(__nv_bfloat162*)&v.x); acc[0] += f.x; acc[1] += f.y;
    f = __bfloat1622float2(*(__nv_bfloat162*)&v.y); acc[2] += f.x; acc[3] += f.y;
    f = __bfloat1622float2(*(__nv_bfloat162*)&v.z); acc[4] += f.x; acc[5] += f.y;
    f = __bfloat1622float2(*(__nv_bfloat162*)&v.w); acc[6] += f.x; acc[7] += f.y;
}

#define LDSM_X4(r0, r1, r2, r3, addr) \
    asm volatile("ldmatrix.sync.aligned.m8n8.x4.shared.b16 {%0,%1,%2,%3}, [%4];" \
                 : "=r"(r0), "=r"(r1), "=r"(r2), "=r"(r3) : "r"(addr))
#define LDSM_X4T(r0, r1, r2, r3, addr) \
    asm volatile("ldmatrix.sync.aligned.m8n8.x4.trans.shared.b16 {%0,%1,%2,%3}, [%4];" \
                 : "=r"(r0), "=r"(r1), "=r"(r2), "=r"(r3) : "r"(addr))
#define MMA_BF16(c, a, b) \
    asm volatile("mma.sync.aligned.m16n8k16.row.col.f32.bf16.bf16.f32 " \
                 "{%0,%1,%2,%3}, {%4,%5,%6,%7}, {%8,%9}, {%0,%1,%2,%3};" \
                 : "+f"((c)[0]), "+f"((c)[1]), "+f"((c)[2]), "+f"((c)[3]) \
                 : "r"((a)[0]), "r"((a)[1]), "r"((a)[2]), "r"((a)[3]), \
                   "r"((b)[0]), "r"((b)[1]))
#define CP_ASYNC16(saddr, gptr) \
    asm volatile("cp.async.cg.shared.global [%0], [%1], 16;" :: "r"(saddr), "l"(gptr))
#define CP_COMMIT() asm volatile("cp.async.commit_group;")
#define CP_WAIT(n)  asm volatile("cp.async.wait_group %0;" :: "n"(n))

// ---------------- merged prep + hist: weight split, lookback reset, histogram + rank ----------------
__global__ void k_prep_hist(
    const float* __restrict__ W1s, const float* __restrict__ W1n,
    const float* __restrict__ W2s, const float* __restrict__ W2n,
    const int* __restrict__ dst, int E)
{
    int i = blockIdx.x * blockDim.x + threadIdx.x;
    if (i < 64) g_lb[i] = 0ull;
    if (i < 4 * 32768) {
        int a = i >> 15, r = i & 32767;
        const float* W = (a == 0) ? W1s : (a == 1) ? W1n : (a == 2) ? W2s : W2n;
        __nv_bfloat16* hi = (a == 0) ? g_w1s_h : (a == 1) ? g_w1n_h : (a == 2) ? g_w2s_h : g_w2n_h;
        __nv_bfloat16* lo = (a == 0) ? g_w1s_l : (a == 1) ? g_w1n_l : (a == 2) ? g_w2s_l : g_w2n_l;
        float w = W[r];
        __nv_bfloat16 h = __float2bfloat16_rn(w);
        hi[r] = h;
        lo[r] = __float2bfloat16_rn(w - __bfloat162float(h));
    }
    if (i < E) g_rank[i] = atomicAdd(&g_cnt[dst[i]], 1);
}

// ---------------- single-pass scan with decoupled lookback ----------------
// g_cnt -> exclusive prefix (rowptr); self-zeroes g_cnt for next replay.
__global__ void k_scan() {
    __shared__ int wscan[32];
    __shared__ int s_prefix;
    int t = threadIdx.x, lane = t & 31, w = t >> 5;
    int b = blockIdx.x;
    int idx = b * 1024 + t;

    int v = (idx < N_NODES) ? g_cnt[idx] : 0;
    if (idx < N_NODES) g_cnt[idx] = 0;     // reset for next execution

    int iv = v;
#pragma unroll
    for (int off = 1; off < 32; off <<= 1) {
        int u = __shfl_up_sync(0xFFFFFFFFu, iv, off);
        if (lane >= off) iv += u;
    }
    if (lane == 31) wscan[w] = iv;
    __syncthreads();
    if (w == 0) {
        int s = wscan[lane];
#pragma unroll
        for (int off = 1; off < 32; off <<= 1) {
            int u = __shfl_up_sync(0xFFFFFFFFu, s, off);
            if (lane >= off) s += u;
        }
        wscan[lane] = s;
    }
    __syncthreads();
    int warp_off = (w == 0) ? 0 : wscan[w - 1];
    int tot = wscan[31];

    if (t == 0) {
        if (b == 0) {
            s_prefix = 0;
            atomicExch(&g_lb[0], (2ull << 32) | (unsigned int)tot);
        } else {
            atomicExch(&g_lb[b], (1ull << 32) | (unsigned int)tot);
            int run = 0;
            int j = b - 1;
            for (;;) {
                unsigned long long e;
                do { e = *(volatile unsigned long long*)&g_lb[j]; } while ((e >> 32) == 0ull);
                run += (int)(unsigned int)e;
                if ((e >> 32) == 2ull) break;
                j--;
            }
            s_prefix = run;
            atomicExch(&g_lb[b], (2ull << 32) | (unsigned int)(run + tot));
            if (b == NBLK_SCAN - 1) g_rowptr[N_NODES] = run + tot;
        }
    }
    __syncthreads();
    if (idx < N_NODES) {
        g_rowptr[idx] = iv - v + warp_off + s_prefix;
    }
}

// atomic-free fill using precomputed ranks
__global__ void k_fill(const int* __restrict__ src, const int* __restrict__ dst, int E) {
    int e = blockIdx.x * blockDim.x + threadIdx.x;
    if (e < E) {
        int d = dst[e];
        g_csr_src[g_rowptr[d] + g_rank[e]] = src[e];
    }
}

// ---------------- layer-1 aggregation: half-warp per node, fp32 gather ----------------
__global__ void k_agg128(const float* __restrict__ feat, float* __restrict__ out) {
    int halves_per_blk = blockDim.x >> 4;
    int n = blockIdx.x * halves_per_blk + (threadIdx.x >> 4);
    if (n >= N_NODES) return;
    int lane = threadIdx.x & 15;
    int beg = g_rowptr[n], end = g_rowptr[n + 1];

    float4 aA0 = {0.f, 0.f, 0.f, 0.f}, aB0 = {0.f, 0.f, 0.f, 0.f};
    float4 aA1 = {0.f, 0.f, 0.f, 0.f}, aB1 = {0.f, 0.f, 0.f, 0.f};
    int j = beg;
    for (; j + 1 < end; j += 2) {
        int s0 = g_csr_src[j];
        int s1 = g_csr_src[j + 1];
        const float4* r0 = (const float4*)(feat + (size_t)s0 * 128);
        const float4* r1 = (const float4*)(feat + (size_t)s1 * 128);
        float4 vA0 = __ldg(&r0[lane]);
        float4 vB0 = __ldg(&r0[lane + 16]);
        float4 vA1 = __ldg(&r1[lane]);
        float4 vB1 = __ldg(&r1[lane + 16]);
        aA0.x += vA0.x; aA0.y += vA0.y; aA0.z += vA0.z; aA0.w += vA0.w;
        aB0.x += vB0.x; aB0.y += vB0.y; aB0.z += vB0.z; aB0.w += vB0.w;
        aA1.x += vA1.x; aA1.y += vA1.y; aA1.z += vA1.z; aA1.w += vA1.w;
        aB1.x += vB1.x; aB1.y += vB1.y; aB1.z += vB1.z; aB1.w += vB1.w;
    }
    if (j < end) {
        int s0 = g_csr_src[j];
        const float4* r0 = (const float4*)(feat + (size_t)s0 * 128);
        float4 vA0 = __ldg(&r0[lane]);
        float4 vB0 = __ldg(&r0[lane + 16]);
        aA0.x += vA0.x; aA0.y += vA0.y; aA0.z += vA0.z; aA0.w += vA0.w;
        aB0.x += vB0.x; aB0.y += vB0.y; aB0.z += vB0.z; aB0.w += vB0.w;
    }
    aA0.x += aA1.x; aA0.y += aA1.y; aA0.z += aA1.z; aA0.w += aA1.w;
    aB0.x += aB1.x; aB0.y += aB1.y; aB0.z += aB1.z; aB0.w += aB1.w;
    int deg = end - beg;
    float inv = (deg > 0) ? 1.f / (float)deg : 0.f;
    float4* orow = (float4*)(out + (size_t)n * 128);
    float4 oA = {aA0.x * inv, aA0.y * inv, aA0.z * inv, aA0.w * inv};
    float4 oB = {aB0.x * inv, aB0.y * inv, aB0.z * inv, aB0.w * inv};
    orow[lane] = oA;
    orow[lane + 16] = oB;
}

// ================= bf16x3 mma.sync GEMMs: swizzled-B double-buffer =================
#define A_TILE_B 10240
#define B_TILE_B 4096

// -------- layer 1: C = relu(A1@B1 + A2@B2 + bias) --------
__global__ void __launch_bounds__(256) k_mm_dual(
    const float* __restrict__ A1, const float* __restrict__ A2,
    const __nv_bfloat16* __restrict__ B1h, const __nv_bfloat16* __restrict__ B1l,
    const __nv_bfloat16* __restrict__ B2h, const __nv_bfloat16* __restrict__ B2l,
    const float* __restrict__ bias, float* __restrict__ C,
    int M, int N, int K)
{
    extern __shared__ char smem[];
    const int OA1H = 0, OA1L = A_TILE_B, OA2H = 2 * A_TILE_B, OA2L = 3 * A_TILE_B;
    const int OB_BASE = 4 * A_TILE_B;
    uint32_t sb = smem_u32(smem);

    int tid = threadIdx.x, lane = tid & 31, wid = tid >> 5;
    int wm = wid & 3, wn = wid >> 2;
    int bm = blockIdx.y * 128, bn = blockIdx.x * 64;
    const int nch = K >> 5;

    int brow = tid >> 3, bseg = tid & 7;
    uint32_t bso = (uint32_t)(brow * 128 + ((bseg ^ (brow & 7)) << 4));
    const __nv_bfloat16* gB[4] = {B1h, B1l, B2h, B2l};

    float acc[2][4][4];
#pragma unroll
    for (int i = 0; i < 2; i++)
#pragma unroll
        for (int j = 0; j < 4; j++)
#pragma unroll
            for (int q = 0; q < 4; q++) acc[i][j][q] = 0.f;

    {
        size_t ge = (size_t)brow * N + bn + bseg * 8;
#pragma unroll
        for (int t = 0; t < 4; t++)
            CP_ASYNC16(sb + OB_BASE + t * B_TILE_B + bso, gB[t] + ge);
        CP_COMMIT();
    }

    for (int chunk = 0; chunk < nch; chunk++) {
        int k0 = chunk << 5;
        int obuf = OB_BASE + (chunk & 1) * 4 * B_TILE_B;

#pragma unroll
        for (int q = 0; q < 4; q++) {
            int slot = tid + q * 256;
            int row = slot >> 3, k4 = (slot & 7) * 4;
            int gr = bm + row;
            float4 v1 = {0.f, 0.f, 0.f, 0.f}, v2 = {0.f, 0.f, 0.f, 0.f};
            if (gr < M) {
                v1 = *(const float4*)(A1 + (size_t)gr * K + k0 + k4);
                v2 = *(const float4*)(A2 + (size_t)gr * K + k0 + k4);
            }
            uint32_t h[2], l[2];
            int si = row * 20 + (k4 >> 1);
            split4(v1, h, l);
            ((uint32_t*)(smem + OA1H))[si] = h[0];
            ((uint32_t*)(smem + OA1H))[si + 1] = h[1];
            ((uint32_t*)(smem + OA1L))[si] = l[0];
            ((uint32_t*)(smem + OA1L))[si + 1] = l[1];
            split4(v2, h, l);
            ((uint32_t*)(smem + OA2H))[si] = h[0];
            ((uint32_t*)(smem + OA2H))[si + 1] = h[1];
            ((uint32_t*)(smem + OA2L))[si] = l[0];
            ((uint32_t*)(smem + OA2L))[si + 1] = l[1];
        }

        if (chunk + 1 < nch) {
            int nbuf = OB_BASE + ((chunk + 1) & 1) * 4 * B_TILE_B;
            size_t ge = (size_t)(((chunk + 1) << 5) + brow) * N + bn + bseg * 8;
#pragma unroll
            for (int t = 0; t < 4; t++)
                CP_ASYNC16(sb + nbuf + t * B_TILE_B + bso, gB[t] + ge);
            CP_COMMIT();
            CP_WAIT(1);
        } else {
            CP_WAIT(0);
        }
        __syncthreads();

#pragma unroll
        for (int kk = 0; kk < 2; kk++) {
            uint32_t fa1h[2][4], fa1l[2][4], fa2h[2][4], fa2l[2][4];
#pragma unroll
            for (int mi = 0; mi < 2; mi++) {
                uint32_t aoff = (uint32_t)((wm * 32 + mi * 16 + (lane & 15)) * 80 +
                                           (lane >> 4) * 16 + kk * 32);
                LDSM_X4(fa1h[mi][0], fa1h[mi][1], fa1h[mi][2], fa1h[mi][3], sb + OA1H + aoff);
                LDSM_X4(fa1l[mi][0], fa1l[mi][1], fa1l[mi][2], fa1l[mi][3], sb + OA1L + aoff);
                LDSM_X4(fa2h[mi][0], fa2h[mi][1], fa2h[mi][2], fa2h[mi][3], sb + OA2H + aoff);
                LDSM_X4(fa2l[mi][0], fa2l[mi][1], fa2l[mi][2], fa2l[mi][3], sb + OA2L + aoff);
            }
            uint32_t fb1h[4][2], fb1l[4][2], fb2h[4][2], fb2l[4][2];
#pragma unroll
            for (int np = 0; np < 2; np++) {
                int r = kk * 16 + (lane & 7) + ((lane >> 3) & 1) * 8;
                int cu = wn * 4 + np * 2 + (lane >> 4);
                uint32_t boff = (uint32_t)(r * 128 + ((cu ^ (r & 7)) << 4));
                LDSM_X4T(fb1h[2 * np][0], fb1h[2 * np][1], fb1h[2 * np + 1][0], fb1h[2 * np + 1][1], sb + obuf + 0 * B_TILE_B + boff);
                LDSM_X4T(fb1l[2 * np][0], fb1l[2 * np][1], fb1l[2 * np + 1][0], fb1l[2 * np + 1][1], sb + obuf + 1 * B_TILE_B + boff);
                LDSM_X4T(fb2h[2 * np][0], fb2h[2 * np][1], fb2h[2 * np + 1][0], fb2h[2 * np + 1][1], sb + obuf + 2 * B_TILE_B + boff);
                LDSM_X4T(fb2l[2 * np][0], fb2l[2 * np][1], fb2l[2 * np + 1][0], fb2l[2 * np + 1][1], sb + obuf + 3 * B_TILE_B + boff);
            }
#pragma unroll
            for (int mi = 0; mi < 2; mi++)
#pragma unroll
                for (int nj = 0; nj < 4; nj++) {
                    MMA_BF16(acc[mi][nj], fa1h[mi], fb1h[nj]);
                    MMA_BF16(acc[mi][nj], fa1h[mi], fb1l[nj]);
                    MMA_BF16(acc[mi][nj], fa1l[mi], fb1h[nj]);
                    MMA_BF16(acc[mi][nj], fa2h[mi], fb2h[nj]);
                    MMA_BF16(acc[mi][nj], fa2h[mi], fb2l[nj]);
                    MMA_BF16(acc[mi][nj], fa2l[mi], fb2h[nj]);
                }
        }
        __syncthreads();
    }

    int g = lane >> 2, c2 = (lane & 3) * 2;
#pragma unroll
    for (int mi = 0; mi < 2; mi++)
#pragma unroll
        for (int nj = 0; nj < 4; nj++) {
            int col = bn + wn * 32 + nj * 8 + c2;
            float2 bv = *(const float2*)(bias + col);
            int r0 = bm + wm * 32 + mi * 16 + g;
            if (r0 < M) {
                float2 o;
                o.x = fmaxf(acc[mi][nj][0] + bv.x, 0.f);
                o.y = fmaxf(acc[mi][nj][1] + bv.y, 0.f);
                *(float2*)(C + (size_t)r0 * N + col) = o;
            }
            int r1 = r0 + 8;
            if (r1 < M) {
                float2 o;
                o.x = fmaxf(acc[mi][nj][2] + bv.x, 0.f);
                o.y = fmaxf(acc[mi][nj][3] + bv.y, 0.f);
                *(float2*)(C + (size_t)r1 * N + col) = o;
            }
        }
}

// -------- layer 2: S = A@Bs + bias (fp32), T = A@Bt (bf16) --------
__global__ void __launch_bounds__(256) k_mm_pair(
    const float* __restrict__ A,
    const __nv_bfloat16* __restrict__ Bsh, const __nv_bfloat16* __restrict__ Bsl,
    const __nv_bfloat16* __restrict__ Bth, const __nv_bfloat16* __restrict__ Btl,
    const float* __restrict__ bias, float* __restrict__ S, __nv_bfloat16* __restrict__ T,
    int M, int N, int K)
{
    extern __shared__ char smem[];
    const int OAH = 0, OAL = A_TILE_B;
    const int OB_BASE = 2 * A_TILE_B;
    uint32_t sb = smem_u32(smem);

    int tid = threadIdx.x, lane = tid & 31, wid = tid >> 5;
    int wm = wid & 3, wn = wid >> 2;
    int bm = blockIdx.y * 128, bn = blockIdx.x * 64;
    const int nch = K >> 5;

    int brow = tid >> 3, bseg = tid & 7;
    uint32_t bso = (uint32_t)(brow * 128 + ((bseg ^ (brow & 7)) << 4));
    const __nv_bfloat16* gB[4] = {Bsh, Bsl, Bth, Btl};

    float accS[2][4][4], accT[2][4][4];
#pragma unroll
    for (int i = 0; i < 2; i++)
#pragma unroll
        for (int j = 0; j < 4; j++)
#pragma unroll
            for (int q = 0; q < 4; q++) { accS[i][j][q] = 0.f; accT[i][j][q] = 0.f; }

    {
        size_t ge = (size_t)brow * N + bn + bseg * 8;
#pragma unroll
        for (int t = 0; t < 4; t++)
            CP_ASYNC16(sb + OB_BASE + t * B_TILE_B + bso, gB[t] + ge);
        CP_COMMIT();
    }

    for (int chunk = 0; chunk < nch; chunk++) {
        int k0 = chunk << 5;
        int obuf = OB_BASE + (chunk & 1) * 4 * B_TILE_B;

#pragma unroll
        for (int q = 0; q < 4; q++) {
            int slot = tid + q * 256;
            int row = slot >> 3, k4 = (slot & 7) * 4;
            int gr = bm + row;
            float4 v = {0.f, 0.f, 0.f, 0.f};
            if (gr < M) v = *(const float4*)(A + (size_t)gr * K + k0 + k4);
            uint32_t h[2], l[2];
            split4(v, h, l);
            int si = row * 20 + (k4 >> 1);
            ((uint32_t*)(smem + OAH))[si] = h[0];
            ((uint32_t*)(smem + OAH))[si + 1] = h[1];
            ((uint32_t*)(smem + OAL))[si] = l[0];
            ((uint32_t*)(smem + OAL))[si + 1] = l[1];
        }

        if (chunk + 1 < nch) {
            int nbuf = OB_BASE + ((chunk + 1) & 1) * 4 * B_TILE_B;
            size_t ge = (size_t)(((chunk + 1) << 5) + brow) * N + bn + bseg * 8;
#pragma unroll
            for (int t = 0; t < 4; t++)
                CP_ASYNC16(sb + nbuf + t * B_TILE_B + bso, gB[t] + ge);
            CP_COMMIT();
            CP_WAIT(1);
        } else {
            CP_WAIT(0);
        }
        __syncthreads();

#pragma unroll
        for (int kk = 0; kk < 2; kk++) {
            uint32_t fah[2][4], fal[2][4];
#pragma unroll
            for (int mi = 0; mi < 2; mi++) {
                uint32_t aoff = (uint32_t)((wm * 32 + mi * 16 + (lane & 15)) * 80 +
                                           (lane >> 4) * 16 + kk * 32);
                LDSM_X4(fah[mi][0], fah[mi][1], fah[mi][2], fah[mi][3], sb + OAH + aoff);
                LDSM_X4(fal[mi][0], fal[mi][1], fal[mi][2], fal[mi][3], sb + OAL + aoff);
            }
            uint32_t fbsh[4][2], fbsl[4][2], fbth[4][2], fbtl[4][2];
#pragma unroll
            for (int np = 0; np < 2; np++) {
                int r = kk * 16 + (lane & 7) + ((lane >> 3) & 1) * 8;
                int cu = wn * 4 + np * 2 + (lane >> 4);
                uint32_t boff = (uint32_t)(r * 128 + ((cu ^ (r & 7)) << 4));
                LDSM_X4T(fbsh[2 * np][0], fbsh[2 * np][1], fbsh[2 * np + 1][0], fbsh[2 * np + 1][1], sb + obuf + 0 * B_TILE_B + boff);
                LDSM_X4T(fbsl[2 * np][0], fbsl[2 * np][1], fbsl[2 * np + 1][0], fbsl[2 * np + 1][1], sb + obuf + 1 * B_TILE_B + boff);
                LDSM_X4T(fbth[2 * np][0], fbth[2 * np][1], fbth[2 * np + 1][0], fbth[2 * np + 1][1], sb + obuf + 2 * B_TILE_B + boff);
                LDSM_X4T(fbtl[2 * np][0], fbtl[2 * np][1], fbtl[2 * np + 1][0], fbtl[2 * np + 1][1], sb + obuf + 3 * B_TILE_B + boff);
            }
#pragma unroll
            for (int mi = 0; mi < 2; mi++)
#pragma unroll
                for (int nj = 0; nj < 4; nj++) {
                    MMA_BF16(accS[mi][nj], fah[mi], fbsh[nj]);
                    MMA_BF16(accS[mi][nj], fah[mi], fbsl[nj]);
                    MMA_BF16(accS[mi][nj], fal[mi], fbsh[nj]);
                    MMA_BF16(accT[mi][nj], fah[mi], fbth[nj]);
                    MMA_BF16(accT[mi][nj], fah[mi], fbtl[nj]);
                    MMA_BF16(accT[mi][nj], fal[mi], fbth[nj]);
                }
        }
        __syncthreads();
    }

    int g = lane >> 2, c2 = (lane & 3) * 2;
#pragma unroll
    for (int mi = 0; mi < 2; mi++)
#pragma unroll
        for (int nj = 0; nj < 4; nj++) {
            int col = bn + wn * 32 + nj * 8 + c2;
            float2 bv = *(const float2*)(bias + col);
            int r0 = bm + wm * 32 + mi * 16 + g;
            if (r0 < M) {
                float2 os = {accS[mi][nj][0] + bv.x, accS[mi][nj][1] + bv.y};
                *(float2*)(S + (size_t)r0 * N + col) = os;
                ((uint32_t*)T)[((size_t)r0 * N + col) >> 1] =
                    bpack(__float2bfloat16_rn(accT[mi][nj][0]), __float2bfloat16_rn(accT[mi][nj][1]));
            }
            int r1 = r0 + 8;
            if (r1 < M) {
                float2 os = {accS[mi][nj][2] + bv.x, accS[mi][nj][3] + bv.y};
                *(float2*)(S + (size_t)r1 * N + col) = os;
                ((uint32_t*)T)[((size_t)r1 * N + col) >> 1] =
                    bpack(__float2bfloat16_rn(accT[mi][nj][2]), __float2bfloat16_rn(accT[mi][nj][3]));
            }
        }
}

// ---------------- fused layer-2 aggregation + node scores: half-warp, bf16 t2 ----------------
__global__ void k_agg2_scores(const float* __restrict__ Wp) {
    int halves_per_blk = blockDim.x >> 4;
    int n = blockIdx.x * halves_per_blk + (threadIdx.x >> 4);
    if (n >= N_NODES) return;
    int lane = threadIdx.x & 15;
    int beg = g_rowptr[n], end = g_rowptr[n + 1];

    float a0[8] = {0.f, 0.f, 0.f, 0.f, 0.f, 0.f, 0.f, 0.f};
    float a1[8] = {0.f, 0.f, 0.f, 0.f, 0.f, 0.f, 0.f, 0.f};
    int j = beg;
    for (; j + 1 < end; j += 2) {
        int s0 = g_csr_src[j];
        int s1 = g_csr_src[j + 1];
        uint4 v0 = __ldg(&((const uint4*)(g_t2b + (size_t)s0 * 128))[lane]);
        uint4 v1 = __ldg(&((const uint4*)(g_t2b + (size_t)s1 * 128))[lane]);
        acc_bf16x8(a0, v0);
        acc_bf16x8(a1, v1);
    }
    if (j < end) {
        int s0 = g_csr_src[j];
        uint4 v0 = __ldg(&((const uint4*)(g_t2b + (size_t)s0 * 128))[lane]);
        acc_bf16x8(a0, v0);
    }
#pragma unroll
    for (int q = 0; q < 8; q++) a0[q] += a1[q];

    int deg = end - beg;
    float inv = (deg > 0) ? 1.f / (float)deg : 0.f;
    const float4* srow = (const float4*)(g_s2 + (size_t)n * 128);
    float4 sv0 = srow[lane * 2], sv1 = srow[lane * 2 + 1];
    float h[8];
    h[0] = sv0.x + a0[0] * inv; h[1] = sv0.y + a0[1] * inv;
    h[2] = sv0.z + a0[2] * inv; h[3] = sv0.w + a0[3] * inv;
    h[4] = sv1.x + a0[4] * inv; h[5] = sv1.y + a0[5] * inv;
    h[6] = sv1.z + a0[6] * inv; h[7] = sv1.w + a0[7] * inv;

    const float4* wp4 = (const float4*)Wp;
    float4 wa0 = __ldg(&wp4[lane * 2]);
    float4 wa1 = __ldg(&wp4[lane * 2 + 1]);
    float4 wb0 = __ldg(&wp4[32 + lane * 2]);
    float4 wb1 = __ldg(&wp4[32 + lane * 2 + 1]);
    float a = h[0] * wa0.x + h[1] * wa0.y + h[2] * wa0.z + h[3] * wa0.w
            + h[4] * wa1.x + h[5] * wa1.y + h[6] * wa1.z + h[7] * wa1.w;
    float b = h[0] * wb0.x + h[1] * wb0.y + h[2] * wb0.z + h[3] * wb0.w
            + h[4] * wb1.x + h[5] * wb1.y + h[6] * wb1.z + h[7] * wb1.w;
#pragma unroll
    for (int off = 8; off; off >>= 1) {
        a += __shfl_down_sync(0xFFFFFFFFu, a, off, 16);
        b += __shfl_down_sync(0xFFFFFFFFu, b, off, 16);
    }
    if (lane == 0) { g_sA[n] = a; g_sB[n] = b; }
}

__global__ void k_edge_scores(const int* __restrict__ psrc, const int* __restrict__ pdst,
                              const int* __restrict__ nsrc, const int* __restrict__ ndst,
                              const float* __restrict__ bp, float* __restrict__ out,
                              int EP, int EN) {
    int i = blockIdx.x * blockDim.x + threadIdx.x;
    float b = bp[0];
    if (i < EP) {
        out[i] = g_sA[psrc[i]] + g_sB[pdst[i]] + b;
    } else if (i < EP + EN) {
        int j = i - EP;
        out[i] = g_sA[nsrc[j]] + g_sB[ndst[j]] + b;
    }
}

// ---------------- launch ----------------
extern "C" void kernel_launch(void* const* d_in, const int* in_sizes, int n_in,
                              void* d_out, int out_size) {
    const float* x    = (const float*)d_in[0];
    const int* msrc   = (const int*)d_in[1];
    const int* mdst   = (const int*)d_in[2];
    const int* psrc   = (const int*)d_in[3];
    const int* pdst   = (const int*)d_in[4];
    const int* nsrc   = (const int*)d_in[5];
    const int* ndst   = (const int*)d_in[6];
    const float* W1s  = (const float*)d_in[7];
    const float* W1n  = (const float*)d_in[8];
    const float* b1   = (const float*)d_in[9];
    const float* W2s  = (const float*)d_in[10];
    const float* W2n  = (const float*)d_in[11];
    const float* b2   = (const float*)d_in[12];
    const float* Wp   = (const float*)d_in[13];
    const float* bp   = (const float*)d_in[14];
    float* out = (float*)d_out;

    int E  = in_sizes[1];
    int EP = in_sizes[3];
    int EN = in_sizes[5];

    float *p_neigh1, *p_h1, *p_s2;
    __nv_bfloat16* p_t2b;
    cudaGetSymbolAddress((void**)&p_neigh1, g_neigh1);
    cudaGetSymbolAddress((void**)&p_h1,     g_h1);
    cudaGetSymbolAddress((void**)&p_s2,     g_s2);
    cudaGetSymbolAddress((void**)&p_t2b,    g_t2b);

    __nv_bfloat16 *w1sh, *w1sl, *w1nh, *w1nl, *w2sh, *w2sl, *w2nh, *w2nl;
    cudaGetSymbolAddress((void**)&w1sh, g_w1s_h);
    cudaGetSymbolAddress((void**)&w1sl, g_w1s_l);
    cudaGetSymbolAddress((void**)&w1nh, g_w1n_h);
    cudaGetSymbolAddress((void**)&w1nl, g_w1n_l);
    cudaGetSymbolAddress((void**)&w2sh, g_w2s_h);
    cudaGetSymbolAddress((void**)&w2sl, g_w2s_l);
    cudaGetSymbolAddress((void**)&w2nh, g_w2n_h);
    cudaGetSymbolAddress((void**)&w2nl, g_w2n_l);

    const int SMEM_DUAL = 4 * A_TILE_B + 2 * 4 * B_TILE_B;  // 73728
    const int SMEM_PAIR = 2 * A_TILE_B + 2 * 4 * B_TILE_B;  // 53248
    cudaFuncSetAttribute(k_mm_dual, cudaFuncAttributeMaxDynamicSharedMemorySize, SMEM_DUAL);
    cudaFuncSetAttribute(k_mm_pair, cudaFuncAttributeMaxDynamicSharedMemorySize, SMEM_PAIR);

    // merged prep+hist (records ranks), single-pass lookback scan, atomic-free fill
    k_prep_hist<<<(E + 255) / 256, 256>>>(W1s, W1n, W2s, W2n, mdst, E);
    k_scan<<<NBLK_SCAN, 1024>>>();
    k_fill<<<(E + 255) / 256, 256>>>(msrc, mdst, E);

    // layer 1
    k_agg128<<<(N_NODES + 15) / 16, 256>>>(x, p_neigh1);
    {
        dim3 grid(D_HID / 64, (N_NODES + 127) / 128);
        k_mm_dual<<<grid, 256, SMEM_DUAL>>>(x, p_neigh1, w1sh, w1sl, w1nh, w1nl,
                                            b1, p_h1, N_NODES, D_HID, D_IN);
    }
    // layer 2: project then aggregate (t2 stored bf16)
    {
        dim3 grid(D_OUT / 64, (N_NODES + 127) / 128);
        k_mm_pair<<<grid, 256, SMEM_PAIR>>>(p_h1, w2sh, w2sl, w2nh, w2nl,
                                            b2, p_s2, p_t2b, N_NODES, D_OUT, D_HID);
    }
    k_agg2_scores<<<(N_NODES + 15) / 16, 256>>>(Wp);

    // edge scoring
    k_edge_scores<<<(EP + EN + 255) / 256, 256>>>(psrc, pdst, nsrc, ndst, bp, out, EP, EN);
}

// round 17
// speedup vs baseline: 1.1002x; 1.0776x over previous
#include <cuda_runtime.h>
#include <cuda_bf16.h>
#include <cstdint>

#define N_NODES 50000
#define MAX_E   800000
#define D_IN    128
#define D_HID   256
#define D_OUT   128
#define NBLK_SCAN ((N_NODES + 1023) / 1024)   // 49

// ---------------- scratch (static device globals; no allocation) ----------------
__device__ float g_neigh1[(size_t)N_NODES * D_IN];
__device__ float g_h1[(size_t)N_NODES * D_HID];
__device__ float g_s2[(size_t)N_NODES * D_OUT];
__device__ __nv_bfloat16 g_t2b[(size_t)N_NODES * D_OUT];   // t2 in bf16 (gather-only)
__device__ float g_sA[N_NODES];
__device__ float g_sB[N_NODES];
__device__ int   g_cnt[N_NODES];          // zero at load; self-zeroed by k_scan each run
__device__ int   g_rowptr[N_NODES + 1];
__device__ int   g_rank[MAX_E];
__device__ int   g_csr_src[MAX_E];
__device__ unsigned long long g_lb[64];

// tf32-rounded transposed weights, (N, K) row-major fp32 bit patterns
__device__ float g_w1s_t[D_HID * D_IN];
__device__ float g_w1n_t[D_HID * D_IN];
__device__ float g_w2s_t[D_OUT * D_HID];
__device__ float g_w2n_t[D_OUT * D_HID];

// ---------------- helpers ----------------
__device__ __forceinline__ uint32_t smem_u32(const void* p) {
    uint32_t a;
    asm("{ .reg .u64 t; cvta.to.shared.u64 t, %1; cvt.u32.u64 %0, t; }" : "=r"(a) : "l"(p));
    return a;
}
__device__ __forceinline__ uint32_t bpack(__nv_bfloat16 a, __nv_bfloat16 b) {
    return (uint32_t)__bfloat16_as_ushort(a) | ((uint32_t)__bfloat16_as_ushort(b) << 16);
}
__device__ __forceinline__ uint32_t f2tf(float x) {
    uint32_t u;
    asm("cvt.rna.tf32.f32 %0, %1;" : "=r"(u) : "f"(x));
    return u;
}
__device__ __forceinline__ void acc_bf16x8(float* acc, uint4 v) {
    float2 f;
    f = __bfloat1622float2(*(__nv_bfloat162*)&v.x); acc[0] += f.x; acc[1] += f.y;
    f = __bfloat1622float2(*(__nv_bfloat162*)&v.y); acc[2] += f.x; acc[3] += f.y;
    f = __bfloat1622float2(*(__nv_bfloat162*)&v.z); acc[4] += f.x; acc[5] += f.y;
    f = __bfloat1622float2(*(__nv_bfloat162*)&v.w); acc[6] += f.x; acc[7] += f.y;
}

#define LDSM_X4(r0, r1, r2, r3, addr) \
    asm volatile("ldmatrix.sync.aligned.m8n8.x4.shared.b16 {%0,%1,%2,%3}, [%4];" \
                 : "=r"(r0), "=r"(r1), "=r"(r2), "=r"(r3) : "r"(addr))
#define MMA_TF32(c, a, b) \
    asm volatile("mma.sync.aligned.m16n8k8.row.col.f32.tf32.tf32.f32 " \
                 "{%0,%1,%2,%3}, {%4,%5,%6,%7}, {%8,%9}, {%0,%1,%2,%3};" \
                 : "+f"((c)[0]), "+f"((c)[1]), "+f"((c)[2]), "+f"((c)[3]) \
                 : "r"((a)[0]), "r"((a)[1]), "r"((a)[2]), "r"((a)[3]), \
                   "r"((b)[0]), "r"((b)[1]))
#define CP_ASYNC16(saddr, gptr) \
    asm volatile("cp.async.cg.shared.global [%0], [%1], 16;" :: "r"(saddr), "l"(gptr))
#define CP_COMMIT() asm volatile("cp.async.commit_group;")
#define CP_WAIT(n)  asm volatile("cp.async.wait_group %0;" :: "n"(n))

// ---------------- merged prep + hist ----------------
__global__ void k_prep_hist(
    const float* __restrict__ W1s, const float* __restrict__ W1n,
    const float* __restrict__ W2s, const float* __restrict__ W2n,
    const int* __restrict__ dst, int E)
{
    int i = blockIdx.x * blockDim.x + threadIdx.x;
    if (i < 64) g_lb[i] = 0ull;
    if (i < 4 * 32768) {
        int a = i >> 15, r = i & 32767;
        const float* W = (a == 0) ? W1s : (a == 1) ? W1n : (a == 2) ? W2s : W2n;
        float* out = (a == 0) ? g_w1s_t : (a == 1) ? g_w1n_t : (a == 2) ? g_w2s_t : g_w2n_t;
        int nb = (a < 2) ? 8 : 7;              // N = 256 (layer1) or 128 (layer2)
        int Kd = (a < 2) ? 128 : 256;
        int k = r >> nb, n = r & ((1 << nb) - 1);
        ((uint32_t*)out)[n * Kd + k] = f2tf(W[r]);
    }
    if (i < E) g_rank[i] = atomicAdd(&g_cnt[dst[i]], 1);
}

// ---------------- single-pass scan with decoupled lookback ----------------
__global__ void k_scan() {
    __shared__ int wscan[32];
    __shared__ int s_prefix;
    int t = threadIdx.x, lane = t & 31, w = t >> 5;
    int b = blockIdx.x;
    int idx = b * 1024 + t;

    int v = (idx < N_NODES) ? g_cnt[idx] : 0;
    if (idx < N_NODES) g_cnt[idx] = 0;

    int iv = v;
#pragma unroll
    for (int off = 1; off < 32; off <<= 1) {
        int u = __shfl_up_sync(0xFFFFFFFFu, iv, off);
        if (lane >= off) iv += u;
    }
    if (lane == 31) wscan[w] = iv;
    __syncthreads();
    if (w == 0) {
        int s = wscan[lane];
#pragma unroll
        for (int off = 1; off < 32; off <<= 1) {
            int u = __shfl_up_sync(0xFFFFFFFFu, s, off);
            if (lane >= off) s += u;
        }
        wscan[lane] = s;
    }
    __syncthreads();
    int warp_off = (w == 0) ? 0 : wscan[w - 1];
    int tot = wscan[31];

    if (t == 0) {
        if (b == 0) {
            s_prefix = 0;
            atomicExch(&g_lb[0], (2ull << 32) | (unsigned int)tot);
        } else {
            atomicExch(&g_lb[b], (1ull << 32) | (unsigned int)tot);
            int run = 0;
            int j = b - 1;
            for (;;) {
                unsigned long long e;
                do { e = *(volatile unsigned long long*)&g_lb[j]; } while ((e >> 32) == 0ull);
                run += (int)(unsigned int)e;
                if ((e >> 32) == 2ull) break;
                j--;
            }
            s_prefix = run;
            atomicExch(&g_lb[b], (2ull << 32) | (unsigned int)(run + tot));
            if (b == NBLK_SCAN - 1) g_rowptr[N_NODES] = run + tot;
        }
    }
    __syncthreads();
    if (idx < N_NODES) {
        g_rowptr[idx] = iv - v + warp_off + s_prefix;
    }
}

// atomic-free fill using precomputed ranks
__global__ void k_fill(const int* __restrict__ src, const int* __restrict__ dst, int E) {
    int e = blockIdx.x * blockDim.x + threadIdx.x;
    if (e < E) {
        int d = dst[e];
        g_csr_src[g_rowptr[d] + g_rank[e]] = src[e];
    }
}

// ---------------- layer-1 aggregation: half-warp per node, fp32 gather ----------------
__global__ void k_agg128(const float* __restrict__ feat, float* __restrict__ out) {
    int halves_per_blk = blockDim.x >> 4;
    int n = blockIdx.x * halves_per_blk + (threadIdx.x >> 4);
    if (n >= N_NODES) return;
    int lane = threadIdx.x & 15;
    int beg = g_rowptr[n], end = g_rowptr[n + 1];

    float4 aA0 = {0.f, 0.f, 0.f, 0.f}, aB0 = {0.f, 0.f, 0.f, 0.f};
    float4 aA1 = {0.f, 0.f, 0.f, 0.f}, aB1 = {0.f, 0.f, 0.f, 0.f};
    int j = beg;
    for (; j + 1 < end; j += 2) {
        int s0 = g_csr_src[j];
        int s1 = g_csr_src[j + 1];
        const float4* r0 = (const float4*)(feat + (size_t)s0 * 128);
        const float4* r1 = (const float4*)(feat + (size_t)s1 * 128);
        float4 vA0 = __ldg(&r0[lane]);
        float4 vB0 = __ldg(&r0[lane + 16]);
        float4 vA1 = __ldg(&r1[lane]);
        float4 vB1 = __ldg(&r1[lane + 16]);
        aA0.x += vA0.x; aA0.y += vA0.y; aA0.z += vA0.z; aA0.w += vA0.w;
        aB0.x += vB0.x; aB0.y += vB0.y; aB0.z += vB0.z; aB0.w += vB0.w;
        aA1.x += vA1.x; aA1.y += vA1.y; aA1.z += vA1.z; aA1.w += vA1.w;
        aB1.x += vB1.x; aB1.y += vB1.y; aB1.z += vB1.z; aB1.w += vB1.w;
    }
    if (j < end) {
        int s0 = g_csr_src[j];
        const float4* r0 = (const float4*)(feat + (size_t)s0 * 128);
        float4 vA0 = __ldg(&r0[lane]);
        float4 vB0 = __ldg(&r0[lane + 16]);
        aA0.x += vA0.x; aA0.y += vA0.y; aA0.z += vA0.z; aA0.w += vA0.w;
        aB0.x += vB0.x; aB0.y += vB0.y; aB0.z += vB0.z; aB0.w += vB0.w;
    }
    aA0.x += aA1.x; aA0.y += aA1.y; aA0.z += aA1.z; aA0.w += aA1.w;
    aB0.x += aB1.x; aB0.y += aB1.y; aB0.z += aB1.z; aB0.w += aB1.w;
    int deg = end - beg;
    float inv = (deg > 0) ? 1.f / (float)deg : 0.f;
    float4* orow = (float4*)(out + (size_t)n * 128);
    float4 oA = {aA0.x * inv, aA0.y * inv, aA0.z * inv, aA0.w * inv};
    float4 oB = {aB0.x * inv, aB0.y * inv, aB0.z * inv, aB0.w * inv};
    orow[lane] = oA;
    orow[lane + 16] = oB;
}

// ================= tf32 mma.sync GEMMs =================
// CTA tile 128(M) x 64(N), chunk K=32 (128B fp32 rows, XOR-swizzled 16B units).
// 8 warps: wm=wid&3 (M), wn=wid>>2 (N). Warp tile 32x32, mma m16n8k8.
// A: staged with cvt.rna.tf32, 16KB/matrix, single-buffered.
// B: pre-converted tf32 (N,K) global, cp.async, 8KB/matrix, double-buffered.
#define AT_B 16384
#define BT_B 8192

// -------- layer 1: C = relu(A1@B1t^T + A2@B2t^T + bias) --------
__global__ void __launch_bounds__(256) k_mm_dual(
    const float* __restrict__ A1, const float* __restrict__ A2,
    const float* __restrict__ B1t, const float* __restrict__ B2t,
    const float* __restrict__ bias, float* __restrict__ C,
    int M, int N, int K)
{
    extern __shared__ char smem[];
    const int OA1 = 0, OA2 = AT_B;
    const int OB_BASE = 2 * AT_B;          // buf*2*BT_B + mat*BT_B
    uint32_t sb = smem_u32(smem);

    int tid = threadIdx.x, lane = tid & 31, wid = tid >> 5;
    int wm = wid & 3, wn = wid >> 2;
    int bm = blockIdx.y * 128, bn = blockIdx.x * 64;
    const int nch = K >> 5;

    // cp.async slot for B (64 rows x 8 segs = 512 slots per matrix)
    const float* gB[2] = {B1t, B2t};

    // ldmatrix lane decomposition
    int gA = lane >> 3;
    int rA = (lane & 7) + ((gA & 1) << 3);
    int eA = gA >> 1;
    int gBv = lane >> 3;
    int rB = lane & 7;
    int eB = gBv & 1;
    int njg = gBv >> 1;

    float acc[2][4][4];
#pragma unroll
    for (int i = 0; i < 2; i++)
#pragma unroll
        for (int j = 0; j < 4; j++)
#pragma unroll
            for (int q = 0; q < 4; q++) acc[i][j][q] = 0.f;

    // prologue: B chunk0 -> buf0
    {
#pragma unroll
        for (int mat = 0; mat < 2; mat++)
#pragma unroll
            for (int q = 0; q < 2; q++) {
                int slot = tid + q * 256;
                int row = slot >> 3, seg = slot & 7;
                uint32_t dsts = sb + OB_BASE + mat * BT_B + row * 128 + (((seg ^ (row & 7))) << 4);
                CP_ASYNC16(dsts, gB[mat] + (size_t)(bn + row) * K + seg * 4);
            }
        CP_COMMIT();
    }

    for (int chunk = 0; chunk < nch; chunk++) {
        int k0 = chunk << 5;
        int obuf = OB_BASE + (chunk & 1) * 2 * BT_B;

        // stage A (cvt to tf32)
#pragma unroll
        for (int q = 0; q < 8; q++) {
            const int mat = q >> 2;
            int slot = tid + (q & 3) * 256;
            int row = slot >> 3, seg = slot & 7;
            int gr = bm + row;
            float4 v = {0.f, 0.f, 0.f, 0.f};
            const float* Ap = (mat == 0) ? A1 : A2;
            if (gr < M) v = *(const float4*)(Ap + (size_t)gr * K + k0 + seg * 4);
            uint4 tv;
            tv.x = f2tf(v.x); tv.y = f2tf(v.y); tv.z = f2tf(v.z); tv.w = f2tf(v.w);
            *(uint4*)(smem + ((mat == 0) ? OA1 : OA2) + row * 128 + ((seg ^ (row & 7)) << 4)) = tv;
        }

        // prefetch next B
        if (chunk + 1 < nch) {
            int nbuf = OB_BASE + ((chunk + 1) & 1) * 2 * BT_B;
            int k0n = (chunk + 1) << 5;
#pragma unroll
            for (int mat = 0; mat < 2; mat++)
#pragma unroll
                for (int q = 0; q < 2; q++) {
                    int slot = tid + q * 256;
                    int row = slot >> 3, seg = slot & 7;
                    uint32_t dsts = sb + nbuf + mat * BT_B + row * 128 + ((seg ^ (row & 7)) << 4);
                    CP_ASYNC16(dsts, gB[mat] + (size_t)(bn + row) * K + k0n + seg * 4);
                }
            CP_COMMIT();
            CP_WAIT(1);
        } else {
            CP_WAIT(0);
        }
        __syncthreads();

#pragma unroll
        for (int ks = 0; ks < 4; ks++) {
            uint32_t fa1[2][4], fa2[2][4];
#pragma unroll
            for (int mi = 0; mi < 2; mi++) {
                int row = wm * 32 + mi * 16 + rA;
                int seg = 2 * ks + eA;
                uint32_t aoff = (uint32_t)(row * 128 + ((seg ^ (row & 7)) << 4));
                LDSM_X4(fa1[mi][0], fa1[mi][1], fa1[mi][2], fa1[mi][3], sb + OA1 + aoff);
                LDSM_X4(fa2[mi][0], fa2[mi][1], fa2[mi][2], fa2[mi][3], sb + OA2 + aoff);
            }
#pragma unroll
            for (int p = 0; p < 2; p++) {
                int rowb = wn * 32 + (p * 2 + njg) * 8 + rB;
                int segb = 2 * ks + eB;
                uint32_t boff = (uint32_t)(rowb * 128 + ((segb ^ (rowb & 7)) << 4));
                uint32_t fb1[4], fb2[4];
                LDSM_X4(fb1[0], fb1[1], fb1[2], fb1[3], sb + obuf + 0 * BT_B + boff);
                LDSM_X4(fb2[0], fb2[1], fb2[2], fb2[3], sb + obuf + 1 * BT_B + boff);
#pragma unroll
                for (int mi = 0; mi < 2; mi++) {
                    MMA_TF32(acc[mi][2 * p],     fa1[mi], &fb1[0]);
                    MMA_TF32(acc[mi][2 * p + 1], fa1[mi], &fb1[2]);
                    MMA_TF32(acc[mi][2 * p],     fa2[mi], &fb2[0]);
                    MMA_TF32(acc[mi][2 * p + 1], fa2[mi], &fb2[2]);
                }
            }
        }
        __syncthreads();
    }

    int g = lane >> 2, c2 = (lane & 3) * 2;
#pragma unroll
    for (int mi = 0; mi < 2; mi++)
#pragma unroll
        for (int nj = 0; nj < 4; nj++) {
            int col = bn + wn * 32 + nj * 8 + c2;
            float2 bv = *(const float2*)(bias + col);
            int r0 = bm + wm * 32 + mi * 16 + g;
            if (r0 < M) {
                float2 o;
                o.x = fmaxf(acc[mi][nj][0] + bv.x, 0.f);
                o.y = fmaxf(acc[mi][nj][1] + bv.y, 0.f);
                *(float2*)(C + (size_t)r0 * N + col) = o;
            }
            int r1 = r0 + 8;
            if (r1 < M) {
                float2 o;
                o.x = fmaxf(acc[mi][nj][2] + bv.x, 0.f);
                o.y = fmaxf(acc[mi][nj][3] + bv.y, 0.f);
                *(float2*)(C + (size_t)r1 * N + col) = o;
            }
        }
}

// -------- layer 2: S = A@Bs^T + bias (fp32), T = A@Bt^T (bf16) --------
__global__ void __launch_bounds__(256) k_mm_pair(
    const float* __restrict__ A,
    const float* __restrict__ Bst, const float* __restrict__ Btt,
    const float* __restrict__ bias, float* __restrict__ S, __nv_bfloat16* __restrict__ T,
    int M, int N, int K)
{
    extern __shared__ char smem[];
    const int OA = 0;
    const int OB_BASE = AT_B;
    uint32_t sb = smem_u32(smem);

    int tid = threadIdx.x, lane = tid & 31, wid = tid >> 5;
    int wm = wid & 3, wn = wid >> 2;
    int bm = blockIdx.y * 128, bn = blockIdx.x * 64;
    const int nch = K >> 5;

    const float* gB[2] = {Bst, Btt};

    int gA = lane >> 3;
    int rA = (lane & 7) + ((gA & 1) << 3);
    int eA = gA >> 1;
    int gBv = lane >> 3;
    int rB = lane & 7;
    int eB = gBv & 1;
    int njg = gBv >> 1;

    float accS[2][4][4], accT[2][4][4];
#pragma unroll
    for (int i = 0; i < 2; i++)
#pragma unroll
        for (int j = 0; j < 4; j++)
#pragma unroll
            for (int q = 0; q < 4; q++) { accS[i][j][q] = 0.f; accT[i][j][q] = 0.f; }

    {
#pragma unroll
        for (int mat = 0; mat < 2; mat++)
#pragma unroll
            for (int q = 0; q < 2; q++) {
                int slot = tid + q * 256;
                int row = slot >> 3, seg = slot & 7;
                uint32_t dsts = sb + OB_BASE + mat * BT_B + row * 128 + ((seg ^ (row & 7)) << 4);
                CP_ASYNC16(dsts, gB[mat] + (size_t)(bn + row) * K + seg * 4);
            }
        CP_COMMIT();
    }

    for (int chunk = 0; chunk < nch; chunk++) {
        int k0 = chunk << 5;
        int obuf = OB_BASE + (chunk & 1) * 2 * BT_B;

#pragma unroll
        for (int q = 0; q < 4; q++) {
            int slot = tid + q * 256;
            int row = slot >> 3, seg = slot & 7;
            int gr = bm + row;
            float4 v = {0.f, 0.f, 0.f, 0.f};
            if (gr < M) v = *(const float4*)(A + (size_t)gr * K + k0 + seg * 4);
            uint4 tv;
            tv.x = f2tf(v.x); tv.y = f2tf(v.y); tv.z = f2tf(v.z); tv.w = f2tf(v.w);
            *(uint4*)(smem + OA + row * 128 + ((seg ^ (row & 7)) << 4)) = tv;
        }

        if (chunk + 1 < nch) {
            int nbuf = OB_BASE + ((chunk + 1) & 1) * 2 * BT_B;
            int k0n = (chunk + 1) << 5;
#pragma unroll
            for (int mat = 0; mat < 2; mat++)
#pragma unroll
                for (int q = 0; q < 2; q++) {
                    int slot = tid + q * 256;
                    int row = slot >> 3, seg = slot & 7;
                    uint32_t dsts = sb + nbuf + mat * BT_B + row * 128 + ((seg ^ (row & 7)) << 4);
                    CP_ASYNC16(dsts, gB[mat] + (size_t)(bn + row) * K + k0n + seg * 4);
                }
            CP_COMMIT();
            CP_WAIT(1);
        } else {
            CP_WAIT(0);
        }
        __syncthreads();

#pragma unroll
        for (int ks = 0; ks < 4; ks++) {
            uint32_t fa[2][4];
#pragma unroll
            for (int mi = 0; mi < 2; mi++) {
                int row = wm * 32 + mi * 16 + rA;
                int seg = 2 * ks + eA;
                uint32_t aoff = (uint32_t)(row * 128 + ((seg ^ (row & 7)) << 4));
                LDSM_X4(fa[mi][0], fa[mi][1], fa[mi][2], fa[mi][3], sb + OA + aoff);
            }
#pragma unroll
            for (int p = 0; p < 2; p++) {
                int rowb = wn * 32 + (p * 2 + njg) * 8 + rB;
                int segb = 2 * ks + eB;
                uint32_t boff = (uint32_t)(rowb * 128 + ((segb ^ (rowb & 7)) << 4));
                uint32_t fbs[4], fbt[4];
                LDSM_X4(fbs[0], fbs[1], fbs[2], fbs[3], sb + obuf + 0 * BT_B + boff);
                LDSM_X4(fbt[0], fbt[1], fbt[2], fbt[3], sb + obuf + 1 * BT_B + boff);
#pragma unroll
                for (int mi = 0; mi < 2; mi++) {
                    MMA_TF32(accS[mi][2 * p],     fa[mi], &fbs[0]);
                    MMA_TF32(accS[mi][2 * p + 1], fa[mi], &fbs[2]);
                    MMA_TF32(accT[mi][2 * p],     fa[mi], &fbt[0]);
                    MMA_TF32(accT[mi][2 * p + 1], fa[mi], &fbt[2]);
                }
            }
        }
        __syncthreads();
    }

    int g = lane >> 2, c2 = (lane & 3) * 2;
#pragma unroll
    for (int mi = 0; mi < 2; mi++)
#pragma unroll
        for (int nj = 0; nj < 4; nj++) {
            int col = bn + wn * 32 + nj * 8 + c2;
            float2 bv = *(const float2*)(bias + col);
            int r0 = bm + wm * 32 + mi * 16 + g;
            if (r0 < M) {
                float2 os = {accS[mi][nj][0] + bv.x, accS[mi][nj][1] + bv.y};
                *(float2*)(S + (size_t)r0 * N + col) = os;
                ((uint32_t*)T)[((size_t)r0 * N + col) >> 1] =
                    bpack(__float2bfloat16_rn(accT[mi][nj][0]), __float2bfloat16_rn(accT[mi][nj][1]));
            }
            int r1 = r0 + 8;
            if (r1 < M) {
                float2 os = {accS[mi][nj][2] + bv.x, accS[mi][nj][3] + bv.y};
                *(float2*)(S + (size_t)r1 * N + col) = os;
                ((uint32_t*)T)[((size_t)r1 * N + col) >> 1] =
                    bpack(__float2bfloat16_rn(accT[mi][nj][2]), __float2bfloat16_rn(accT[mi][nj][3]));
            }
        }
}

// ---------------- fused layer-2 aggregation + node scores: half-warp, bf16 t2 ----------------
__global__ void k_agg2_scores(const float* __restrict__ Wp) {
    int halves_per_blk = blockDim.x >> 4;
    int n = blockIdx.x * halves_per_blk + (threadIdx.x >> 4);
    if (n >= N_NODES) return;
    int lane = threadIdx.x & 15;
    int beg = g_rowptr[n], end = g_rowptr[n + 1];

    float a0[8] = {0.f, 0.f, 0.f, 0.f, 0.f, 0.f, 0.f, 0.f};
    float a1[8] = {0.f, 0.f, 0.f, 0.f, 0.f, 0.f, 0.f, 0.f};
    int j = beg;
    for (; j + 1 < end; j += 2) {
        int s0 = g_csr_src[j];
        int s1 = g_csr_src[j + 1];
        uint4 v0 = __ldg(&((const uint4*)(g_t2b + (size_t)s0 * 128))[lane]);
        uint4 v1 = __ldg(&((const uint4*)(g_t2b + (size_t)s1 * 128))[lane]);
        acc_bf16x8(a0, v0);
        acc_bf16x8(a1, v1);
    }
    if (j < end) {
        int s0 = g_csr_src[j];
        uint4 v0 = __ldg(&((const uint4*)(g_t2b + (size_t)s0 * 128))[lane]);
        acc_bf16x8(a0, v0);
    }
#pragma unroll
    for (int q = 0; q < 8; q++) a0[q] += a1[q];

    int deg = end - beg;
    float inv = (deg > 0) ? 1.f / (float)deg : 0.f;
    const float4* srow = (const float4*)(g_s2 + (size_t)n * 128);
    float4 sv0 = srow[lane * 2], sv1 = srow[lane * 2 + 1];
    float h[8];
    h[0] = sv0.x + a0[0] * inv; h[1] = sv0.y + a0[1] * inv;
    h[2] = sv0.z + a0[2] * inv; h[3] = sv0.w + a0[3] * inv;
    h[4] = sv1.x + a0[4] * inv; h[5] = sv1.y + a0[5] * inv;
    h[6] = sv1.z + a0[6] * inv; h[7] = sv1.w + a0[7] * inv;

    const float4* wp4 = (const float4*)Wp;
    float4 wa0 = __ldg(&wp4[lane * 2]);
    float4 wa1 = __ldg(&wp4[lane * 2 + 1]);
    float4 wb0 = __ldg(&wp4[32 + lane * 2]);
    float4 wb1 = __ldg(&wp4[32 + lane * 2 + 1]);
    float a = h[0] * wa0.x + h[1] * wa0.y + h[2] * wa0.z + h[3] * wa0.w
            + h[4] * wa1.x + h[5] * wa1.y + h[6] * wa1.z + h[7] * wa1.w;
    float b = h[0] * wb0.x + h[1] * wb0.y + h[2] * wb0.z + h[3] * wb0.w
            + h[4] * wb1.x + h[5] * wb1.y + h[6] * wb1.z + h[7] * wb1.w;
#pragma unroll
    for (int off = 8; off; off >>= 1) {
        a += __shfl_down_sync(0xFFFFFFFFu, a, off, 16);
        b += __shfl_down_sync(0xFFFFFFFFu, b, off, 16);
    }
    if (lane == 0) { g_sA[n] = a; g_sB[n] = b; }
}

__global__ void k_edge_scores(const int* __restrict__ psrc, const int* __restrict__ pdst,
                              const int* __restrict__ nsrc, const int* __restrict__ ndst,
                              const float* __restrict__ bp, float* __restrict__ out,
                              int EP, int EN) {
    int i = blockIdx.x * blockDim.x + threadIdx.x;
    float b = bp[0];
    if (i < EP) {
        out[i] = g_sA[psrc[i]] + g_sB[pdst[i]] + b;
    } else if (i < EP + EN) {
        int j = i - EP;
        out[i] = g_sA[nsrc[j]] + g_sB[ndst[j]] + b;
    }
}

// ---------------- launch ----------------
extern "C" void kernel_launch(void* const* d_in, const int* in_sizes, int n_in,
                              void* d_out, int out_size) {
    const float* x    = (const float*)d_in[0];
    const int* msrc   = (const int*)d_in[1];
    const int* mdst   = (const int*)d_in[2];
    const int* psrc   = (const int*)d_in[3];
    const int* pdst   = (const int*)d_in[4];
    const int* nsrc   = (const int*)d_in[5];
    const int* ndst   = (const int*)d_in[6];
    const float* W1s  = (const float*)d_in[7];
    const float* W1n  = (const float*)d_in[8];
    const float* b1   = (const float*)d_in[9];
    const float* W2s  = (const float*)d_in[10];
    const float* W2n  = (const float*)d_in[11];
    const float* b2   = (const float*)d_in[12];
    const float* Wp   = (const float*)d_in[13];
    const float* bp   = (const float*)d_in[14];
    float* out = (float*)d_out;

    int E  = in_sizes[1];
    int EP = in_sizes[3];
    int EN = in_sizes[5];

    float *p_neigh1, *p_h1, *p_s2;
    __nv_bfloat16* p_t2b;
    cudaGetSymbolAddress((void**)&p_neigh1, g_neigh1);
    cudaGetSymbolAddress((void**)&p_h1,     g_h1);
    cudaGetSymbolAddress((void**)&p_s2,     g_s2);
    cudaGetSymbolAddress((void**)&p_t2b,    g_t2b);

    float *w1st, *w1nt, *w2st, *w2nt;
    cudaGetSymbolAddress((void**)&w1st, g_w1s_t);
    cudaGetSymbolAddress((void**)&w1nt, g_w1n_t);
    cudaGetSymbolAddress((void**)&w2st, g_w2s_t);
    cudaGetSymbolAddress((void**)&w2nt, g_w2n_t);

    const int SMEM_DUAL = 2 * AT_B + 2 * 2 * BT_B;  // 65536 -> 3 CTAs/SM
    const int SMEM_PAIR = AT_B + 2 * 2 * BT_B;      // 49152 -> 4 CTAs/SM
    cudaFuncSetAttribute(k_mm_dual, cudaFuncAttributeMaxDynamicSharedMemorySize, SMEM_DUAL);
    cudaFuncSetAttribute(k_mm_pair, cudaFuncAttributeMaxDynamicSharedMemorySize, SMEM_PAIR);

    // merged prep+hist (tf32 transpose + ranks), lookback scan, atomic-free fill
    k_prep_hist<<<(E + 255) / 256, 256>>>(W1s, W1n, W2s, W2n, mdst, E);
    k_scan<<<NBLK_SCAN, 1024>>>();
    k_fill<<<(E + 255) / 256, 256>>>(msrc, mdst, E);

    // layer 1
    k_agg128<<<(N_NODES + 15) / 16, 256>>>(x, p_neigh1);
    {
        dim3 grid(D_HID / 64, (N_NODES + 127) / 128);
        k_mm_dual<<<grid, 256, SMEM_DUAL>>>(x, p_neigh1, w1st, w1nt,
                                            b1, p_h1, N_NODES, D_HID, D_IN);
    }
    // layer 2: project then aggregate (t2 stored bf16)
    {
        dim3 grid(D_OUT / 64, (N_NODES + 127) / 128);
        k_mm_pair<<<grid, 256, SMEM_PAIR>>>(p_h1, w2st, w2nt,
                                            b2, p_s2, p_t2b, N_NODES, D_OUT, D_HID);
    }
    k_agg2_scores<<<(N_NODES + 15) / 16, 256>>>(Wp);

    // edge scoring
    k_edge_scores<<<(EP + EN + 255) / 256, 256>>>(psrc, pdst, nsrc, ndst, bp, out, EP, EN);
}